// round 13
// baseline (speedup 1.0000x reference)
#include <cuda_runtime.h>
#include <cuda_fp16.h>
#include <math.h>
#include <stdint.h>

// Problem constants
#define BB   16
#define SSQ  384
#define DDQ  512
#define HHQ  8
#define HDQ  64
#define LLQ  4
#define KKQ  7
#define MMQ  (BB*SSQ)      // 6144 rows
#define BHQ  (BB*HHQ)      // 128 batch*heads

// ---------------- scratch (device globals; no allocation allowed) -----------
__device__ float g_res[MMQ*DDQ];                        // fp32 residual spine
__device__ __half g_xh[MMQ*DDQ];                        // fp16 GEMM A operand
__device__ __half g_yh[MMQ*DDQ];                        // fp16 GEMM Y output
__device__ __half g_wh[9*DDQ*DDQ];                      // fp16 weights
__device__ __half g_qh[MMQ*DDQ];                        // LN16 out (conv input)
__device__ __half g_qkv[3*MMQ*DDQ];                     // fused QKV, head-major

// ================= low-level helpers =========================================
__device__ __forceinline__ uint32_t smem_u32(const void* p) {
    uint32_t a;
    asm("{ .reg .u64 t; cvta.to.shared.u64 t, %1; cvt.u32.u64 %0, t; }" : "=r"(a) : "l"(p));
    return a;
}
__device__ __forceinline__ void cpa16(uint32_t dst, const void* src) {
    asm volatile("cp.async.cg.shared.global [%0], [%1], 16;" :: "r"(dst), "l"(src) : "memory");
}
#define CP_COMMIT() asm volatile("cp.async.commit_group;" ::: "memory")
#define CP_WAIT(n)  asm volatile("cp.async.wait_group %0;" :: "n"(n) : "memory")

__device__ __forceinline__ void ldsm4(uint32_t* r, uint32_t addr) {
    asm volatile("ldmatrix.sync.aligned.m8n8.x4.shared.b16 {%0,%1,%2,%3}, [%4];"
                 : "=r"(r[0]), "=r"(r[1]), "=r"(r[2]), "=r"(r[3]) : "r"(addr));
}
__device__ __forceinline__ void ldsm4t(uint32_t* r, uint32_t addr) {
    asm volatile("ldmatrix.sync.aligned.m8n8.x4.trans.shared.b16 {%0,%1,%2,%3}, [%4];"
                 : "=r"(r[0]), "=r"(r[1]), "=r"(r[2]), "=r"(r[3]) : "r"(addr));
}
__device__ __forceinline__ void hmma(float* d, const uint32_t* a, uint32_t b0, uint32_t b1) {
    asm volatile(
        "mma.sync.aligned.m16n8k16.row.col.f32.f16.f16.f32 "
        "{%0,%1,%2,%3}, {%4,%5,%6,%7}, {%8,%9}, {%0,%1,%2,%3};"
        : "+f"(d[0]), "+f"(d[1]), "+f"(d[2]), "+f"(d[3])
        : "r"(a[0]), "r"(a[1]), "r"(a[2]), "r"(a[3]), "r"(b0), "r"(b1));
}
__device__ __forceinline__ uint32_t packh2(float x, float y) {
    __half2 h = __floats2half2_rn(x, y);
    return *reinterpret_cast<uint32_t*>(&h);
}

// ================= dense GEMM: Y[6144,N] = X@W^T + epilogue ==================
// X fp16 [M,512], W fp16 [N,512]. BM=64 BN=128 BK=64, 256 threads
// (8 warps, 2m x 4n, warp tile 32x32), cp.async 3-stage, 3 blocks/SM.
// MODE 0: Y fp16 (bias+optional relu)   MODE 1: fused QKV scatter   MODE 2: fp32 +res
template<int RELU, int MODE>
__global__ void __launch_bounds__(256, 3)
k_gemm_h(const __half* __restrict__ X, const __half* __restrict__ W,
         const float* __restrict__ bias, const float* __restrict__ bias2,
         const float* __restrict__ bias3, const float* __restrict__ res,
         float* __restrict__ outf, __half* __restrict__ outh) {
    __shared__ __half As[3][64 * 64];
    __shared__ __half Bs[3][128 * 64];
    const int tid = threadIdx.x, lane = tid & 31, wid = tid >> 5;
    const int wm = wid >> 2, wn = wid & 3;
    const int m0 = blockIdx.y * 64, n0 = blockIdx.x * 128;
    float acc[2][4][4] = {};

    const uint32_t aB[3] = { smem_u32(&As[0][0]), smem_u32(&As[1][0]), smem_u32(&As[2][0]) };
    const uint32_t bB[3] = { smem_u32(&Bs[0][0]), smem_u32(&Bs[1][0]), smem_u32(&Bs[2][0]) };

    auto load_stage = [&](int kt, int st) {
        #pragma unroll
        for (int i = 0; i < 2; i++) {
            int q = tid + i * 256; int r = q >> 3, c = q & 7;
            cpa16(aB[st] + r * 128 + ((c ^ (r & 7)) * 16),
                  X + (size_t)(m0 + r) * DDQ + kt * 64 + c * 8);
        }
        #pragma unroll
        for (int i = 0; i < 4; i++) {
            int q = tid + i * 256; int r = q >> 3, c = q & 7;
            cpa16(bB[st] + r * 128 + ((c ^ (r & 7)) * 16),
                  W + (size_t)(n0 + r) * DDQ + kt * 64 + c * 8);
        }
        CP_COMMIT();
    };

    load_stage(0, 0);
    load_stage(1, 1);

    #pragma unroll 1
    for (int kt = 0; kt < 8; kt++) {
        int st = kt % 3;
        if (kt < 7) { CP_WAIT(1); } else { CP_WAIT(0); }
        __syncthreads();
        if (kt + 2 < 8) load_stage(kt + 2, (kt + 2) % 3);

        #pragma unroll
        for (int ks = 0; ks < 4; ks++) {
            uint32_t a[2][4], bfr[2][4];
            #pragma unroll
            for (int mt = 0; mt < 2; mt++) {
                int r = wm * 32 + mt * 16 + (lane & 15);
                int c = ks * 2 + (lane >> 4);
                ldsm4(a[mt], aB[st] + r * 128 + ((c ^ (r & 7)) * 16));
            }
            #pragma unroll
            for (int np = 0; np < 2; np++) {
                int nr = wn * 32 + np * 16 + (lane & 7) + ((lane >> 4) << 3);
                int c = ks * 2 + ((lane >> 3) & 1);
                ldsm4(bfr[np], bB[st] + nr * 128 + ((c ^ (nr & 7)) * 16));
            }
            #pragma unroll
            for (int mt = 0; mt < 2; mt++)
                #pragma unroll
                for (int nt = 0; nt < 4; nt++)
                    hmma(acc[mt][nt], a[mt],
                         bfr[nt >> 1][(nt & 1) * 2], bfr[nt >> 1][(nt & 1) * 2 + 1]);
        }
    }

    // epilogue
    const int mat = n0 >> 9;
    const int col0 = n0 & 511;
    const float* bp = (MODE == 1) ? ((mat == 0) ? bias : ((mat == 1) ? bias2 : bias3)) : bias;
    __half* ob = (MODE == 1) ? (outh + (size_t)mat * MMQ * DDQ) : outh;
    #pragma unroll
    for (int mt = 0; mt < 2; mt++) {
        int r = m0 + wm * 32 + mt * 16 + (lane >> 2);
        #pragma unroll
        for (int nt = 0; nt < 4; nt++) {
            int cl = wn * 32 + nt * 8 + (lane & 3) * 2;
            int col = (MODE == 1) ? (col0 + cl) : 0;
            int n = n0 + cl;
            float b0, b1;
            if (MODE == 1) { b0 = bp[col]; b1 = bp[col + 1]; }
            else           { b0 = bp[n];   b1 = bp[n + 1]; }
            float v00 = acc[mt][nt][0] + b0, v01 = acc[mt][nt][1] + b1;
            float v10 = acc[mt][nt][2] + b0, v11 = acc[mt][nt][3] + b1;
            if (RELU) {
                v00 = fmaxf(v00, 0.f); v01 = fmaxf(v01, 0.f);
                v10 = fmaxf(v10, 0.f); v11 = fmaxf(v11, 0.f);
            }
            if (MODE == 0) {
                *(__half2*)&ob[(size_t)r * DDQ + n] = __floats2half2_rn(v00, v01);
                *(__half2*)&ob[(size_t)(r + 8) * DDQ + n] = __floats2half2_rn(v10, v11);
            } else if (MODE == 1) {
                int h = col >> 6, hd = col & 63;
                int b_ = r / SSQ, s = r % SSQ;
                *(__half2*)&ob[(((size_t)(b_ * HHQ + h) * SSQ + s) << 6) + hd] =
                    __floats2half2_rn(v00, v01);
                int b2 = (r + 8) / SSQ, s2 = (r + 8) % SSQ;
                *(__half2*)&ob[(((size_t)(b2 * HHQ + h) * SSQ + s2) << 6) + hd] =
                    __floats2half2_rn(v10, v11);
            } else {
                float2 r0 = *(const float2*)&res[(size_t)r * DDQ + n];
                float2 r1 = *(const float2*)&res[(size_t)(r + 8) * DDQ + n];
                *(float2*)&outf[(size_t)r * DDQ + n] = make_float2(v00 + r0.x, v01 + r0.y);
                *(float2*)&outf[(size_t)(r + 8) * DDQ + n] = make_float2(v10 + r1.x, v11 + r1.y);
            }
        }
    }
}

// ================= flash attention (double-buffered K/V) =====================
// dynamic smem: Q 16K | K[2] 32K | V[2] 32K | mask 1.5K = 83456 B
#define FLASH_SMEM 83456
__global__ void __launch_bounds__(256)
k_flash(const int* __restrict__ mask) {
    extern __shared__ char fsm[];
    const uint32_t base = smem_u32(fsm);
    const uint32_t qB = base;
    const uint32_t kB0 = base + 16384, kB1 = base + 32768;
    const uint32_t vB0 = base + 49152, vB1 = base + 65536;
    int* misk = (int*)(fsm + 81920);
    const int bh = blockIdx.y, b = bh >> 3, h = bh & 7;
    const __half* Q = g_qkv + (size_t)bh * SSQ * HDQ;
    const __half* K = g_qkv + (size_t)MMQ * DDQ + (size_t)bh * SSQ * HDQ;
    const __half* V = g_qkv + 2 * (size_t)MMQ * DDQ + (size_t)bh * SSQ * HDQ;
    const int m0 = blockIdx.x * 128;
    const int tid = threadIdx.x, lane = tid & 31, w = tid >> 5;

    // mask (all 384) via regular loads
    for (int i = tid; i < SSQ; i += 256) misk[i] = mask[b * SSQ + i];

    auto load_kv = [&](int kc, uint32_t kb, uint32_t vb) {
        #pragma unroll
        for (int i = 0; i < 4; i++) {
            int q = tid + i * 256; int r = q >> 3, c = q & 7;
            cpa16(kb + r * 128 + ((c ^ (r & 7)) * 16),
                  K + (size_t)(kc * 128 + r) * HDQ + c * 8);
            cpa16(vb + r * 128 + ((c ^ (r & 7)) * 16),
                  V + (size_t)(kc * 128 + r) * HDQ + c * 8);
        }
    };

    // prologue: Q + chunk 0 (one group)
    #pragma unroll
    for (int i = 0; i < 4; i++) {
        int q = tid + i * 256; int r = q >> 3, c = q & 7;
        cpa16(qB + r * 128 + ((c ^ (r & 7)) * 16), Q + (size_t)(m0 + r) * HDQ + c * 8);
    }
    load_kv(0, kB0, vB0);
    CP_COMMIT();

    float o[8][4] = {};
    float mrow0 = -3.0e38f, mrow1 = -3.0e38f, lrow0 = 0.f, lrow1 = 0.f;
    const float LOG2E = 1.4426950408889634f;

    #pragma unroll 1
    for (int kc = 0; kc < 3; kc++) {
        uint32_t kb = (kc & 1) ? kB1 : kB0;
        uint32_t vb = (kc & 1) ? vB1 : vB0;
        if (kc < 2) {
            load_kv(kc + 1, (kc & 1) ? kB0 : kB1, (kc & 1) ? vB0 : vB1);
            CP_COMMIT();
            CP_WAIT(1);
        } else {
            CP_WAIT(0);
        }
        __syncthreads();

        float s[16][4] = {};
        #pragma unroll
        for (int ks = 0; ks < 4; ks++) {
            uint32_t a[4];
            { int r = w * 16 + (lane & 15);
              int c = ks * 2 + (lane >> 4);
              ldsm4(a, qB + r * 128 + ((c ^ (r & 7)) * 16)); }
            #pragma unroll
            for (int np = 0; np < 8; np++) {
                uint32_t bf[4];
                int nr = np * 16 + (lane & 7) + ((lane >> 4) << 3);
                int c = ks * 2 + ((lane >> 3) & 1);
                ldsm4(bf, kb + nr * 128 + ((c ^ (nr & 7)) * 16));
                hmma(s[np * 2 + 0], a, bf[0], bf[1]);
                hmma(s[np * 2 + 1], a, bf[2], bf[3]);
            }
        }

        float mx0 = -3.0e38f, mx1 = -3.0e38f;
        #pragma unroll
        for (int nt = 0; nt < 16; nt++) {
            int nc = kc * 128 + nt * 8 + (lane & 3) * 2;
            int f0 = misk[nc], f1 = misk[nc + 1];
            s[nt][0] = f0 ? -1e10f : s[nt][0] * 0.125f;
            s[nt][1] = f1 ? -1e10f : s[nt][1] * 0.125f;
            s[nt][2] = f0 ? -1e10f : s[nt][2] * 0.125f;
            s[nt][3] = f1 ? -1e10f : s[nt][3] * 0.125f;
            mx0 = fmaxf(mx0, fmaxf(s[nt][0], s[nt][1]));
            mx1 = fmaxf(mx1, fmaxf(s[nt][2], s[nt][3]));
        }
        #pragma unroll
        for (int of = 1; of <= 2; of <<= 1) {
            mx0 = fmaxf(mx0, __shfl_xor_sync(0xffffffffu, mx0, of));
            mx1 = fmaxf(mx1, __shfl_xor_sync(0xffffffffu, mx1, of));
        }
        float mn0 = fmaxf(mrow0, mx0), mn1 = fmaxf(mrow1, mx1);
        float al0 = exp2f((mrow0 - mn0) * LOG2E);
        float al1 = exp2f((mrow1 - mn1) * LOG2E);
        mrow0 = mn0; mrow1 = mn1;

        float sum0 = 0.f, sum1 = 0.f;
        #pragma unroll
        for (int nt = 0; nt < 16; nt++) {
            s[nt][0] = exp2f((s[nt][0] - mn0) * LOG2E);
            s[nt][1] = exp2f((s[nt][1] - mn0) * LOG2E);
            s[nt][2] = exp2f((s[nt][2] - mn1) * LOG2E);
            s[nt][3] = exp2f((s[nt][3] - mn1) * LOG2E);
            sum0 += s[nt][0] + s[nt][1];
            sum1 += s[nt][2] + s[nt][3];
        }
        #pragma unroll
        for (int of = 1; of <= 2; of <<= 1) {
            sum0 += __shfl_xor_sync(0xffffffffu, sum0, of);
            sum1 += __shfl_xor_sync(0xffffffffu, sum1, of);
        }
        lrow0 = lrow0 * al0 + sum0;
        lrow1 = lrow1 * al1 + sum1;

        #pragma unroll
        for (int t = 0; t < 8; t++) {
            o[t][0] *= al0; o[t][1] *= al0; o[t][2] *= al1; o[t][3] *= al1;
        }

        #pragma unroll
        for (int kg = 0; kg < 8; kg++) {
            uint32_t a[4];
            a[0] = packh2(s[kg * 2][0],     s[kg * 2][1]);
            a[1] = packh2(s[kg * 2][2],     s[kg * 2][3]);
            a[2] = packh2(s[kg * 2 + 1][0], s[kg * 2 + 1][1]);
            a[3] = packh2(s[kg * 2 + 1][2], s[kg * 2 + 1][3]);
            #pragma unroll
            for (int vn = 0; vn < 4; vn++) {
                uint32_t bf[4];
                int row = kg * 16 + (lane & 7) + ((lane >> 3) & 1) * 8;
                int c = vn * 2 + (lane >> 4);
                ldsm4t(bf, vb + row * 128 + ((c ^ (row & 7)) * 16));
                hmma(o[vn * 2 + 0], a, bf[0], bf[1]);
                hmma(o[vn * 2 + 1], a, bf[2], bf[3]);
            }
        }
        __syncthreads();
    }

    float inv0 = 1.f / lrow0, inv1 = 1.f / lrow1;
    int m = m0 + w * 16 + (lane >> 2);
    #pragma unroll
    for (int t = 0; t < 8; t++) {
        int hd = t * 8 + (lane & 3) * 2;
        *(__half2*)&g_xh[((size_t)(b * SSQ + m)) * DDQ + h * HDQ + hd] =
            __floats2half2_rn(o[t][0] * inv0, o[t][1] * inv0);
        *(__half2*)&g_xh[((size_t)(b * SSQ + m + 8)) * DDQ + h * HDQ + hd] =
            __floats2half2_rn(o[t][2] * inv1, o[t][3] * inv1);
    }
}

// ================= elementwise / reduction kernels ===========================
__inline__ __device__ float blockReduceSum128(float val) {
    __shared__ float sh[4];
    int lane = threadIdx.x & 31, w = threadIdx.x >> 5;
    #pragma unroll
    for (int o = 16; o; o >>= 1) val += __shfl_xor_sync(0xffffffffu, val, o);
    if (lane == 0) sh[w] = val;
    __syncthreads();
    float r = sh[0] + sh[1] + sh[2] + sh[3];
    __syncthreads();
    return r;
}

// fused: res = x + PE; tgt(fp16) = LN(res)*g + b.  one block (128 thr) per row.
__global__ void k_addpos_ln(const float* __restrict__ x, __half* __restrict__ tgt,
                            const float* __restrict__ gm, const float* __restrict__ bt) {
    int row = blockIdx.x;
    int s = row % SSQ;
    int t = threadIdx.x;
    int c = t * 4;
    float4 v = ((const float4*)(x + (size_t)row * DDQ))[t];
    float pe[4];
    #pragma unroll
    for (int i = 0; i < 4; i++) {
        int ci = c + i;
        float inv = exp2f(-((float)(2 * ci) * (1.0f / 512.0f)) * 13.2877123795494f);
        float ang = (float)s * inv;
        pe[i] = (ci & 1) ? cosf(ang) : sinf(ang);
    }
    v.x += pe[0]; v.y += pe[1]; v.z += pe[2]; v.w += pe[3];
    ((float4*)(g_res + (size_t)row * DDQ))[t] = v;

    float sm = v.x + v.y + v.z + v.w;
    float mean = blockReduceSum128(sm) * (1.0f / DDQ);
    float dx = v.x - mean, dy = v.y - mean, dz = v.z - mean, dw = v.w - mean;
    float s2 = dx*dx + dy*dy + dz*dz + dw*dw;
    float var = blockReduceSum128(s2) * (1.0f / DDQ);
    float inv = rsqrtf(var + 1e-5f);
    float ox = dx * inv * gm[c+0] + bt[c+0];
    float oy = dy * inv * gm[c+1] + bt[c+1];
    float oz = dz * inv * gm[c+2] + bt[c+2];
    float ow = dw * inv * gm[c+3] + bt[c+3];
    __half2* hp = (__half2*)(tgt + (size_t)row * DDQ + c);
    hp[0] = __floats2half2_rn(ox, oy);
    hp[1] = __floats2half2_rn(oz, ow);
}

// fused: res += Y(fp16); tgt(fp16) = LN(res)*g + b.  one block (128 thr) per row.
__global__ void k_addln(const __half* __restrict__ y, __half* __restrict__ tgt,
                        const float* __restrict__ gm, const float* __restrict__ bt) {
    int row = blockIdx.x;
    int t = threadIdx.x;
    int c = t * 4;
    float4 v = ((const float4*)(g_res + (size_t)row * DDQ))[t];
    uint2 raw = *(const uint2*)&y[(size_t)row * DDQ + c];
    __half2 y01 = *reinterpret_cast<__half2*>(&raw.x);
    __half2 y23 = *reinterpret_cast<__half2*>(&raw.y);
    float2 f01 = __half22float2(y01), f23 = __half22float2(y23);
    v.x += f01.x; v.y += f01.y; v.z += f23.x; v.w += f23.y;
    ((float4*)(g_res + (size_t)row * DDQ))[t] = v;

    float sm = v.x + v.y + v.z + v.w;
    float mean = blockReduceSum128(sm) * (1.0f / DDQ);
    float dx = v.x - mean, dy = v.y - mean, dz = v.z - mean, dw = v.w - mean;
    float s2 = dx*dx + dy*dy + dz*dz + dw*dw;
    float var = blockReduceSum128(s2) * (1.0f / DDQ);
    float inv = rsqrtf(var + 1e-5f);
    float ox = dx * inv * gm[c+0] + bt[c+0];
    float oy = dy * inv * gm[c+1] + bt[c+1];
    float oz = dz * inv * gm[c+2] + bt[c+2];
    float ow = dw * inv * gm[c+3] + bt[c+3];
    __half2* hp = (__half2*)(tgt + (size_t)row * DDQ + c);
    hp[0] = __floats2half2_rn(ox, oy);
    hp[1] = __floats2half2_rn(oz, ow);
}

// depthwise conv (K=7, same padding), fp16 in/out.
// thread = 8 channels x 4 consecutive s positions (float4 loads).
__global__ void __launch_bounds__(256)
k_dwconv_h(const __half* __restrict__ in, const float* __restrict__ dw) {
    int idx = blockIdx.x * 256 + threadIdx.x;
    if (idx >= (MMQ / 4) * 64) return;
    int c8 = (idx & 63) * 8;
    int bs4 = idx >> 6;
    const int SC = SSQ / 4;             // 96
    int b = bs4 / SC, s0 = (bs4 - b * SC) * 4;

    float w[8][KKQ];
    #pragma unroll
    for (int i = 0; i < 8; i++)
        #pragma unroll
        for (int k = 0; k < KKQ; k++)
            w[i][k] = dw[(c8 + i) * KKQ + k];

    float acc[4][8] = {};
    #pragma unroll
    for (int r = 0; r < 10; r++) {
        int ss = s0 - 3 + r;
        if (ss >= 0 && ss < SSQ) {
            uint4 raw = *(const uint4*)&in[(((size_t)b * SSQ + ss) << 9) + c8];
            float2 f0 = __half22float2(*reinterpret_cast<__half2*>(&raw.x));
            float2 f1 = __half22float2(*reinterpret_cast<__half2*>(&raw.y));
            float2 f2 = __half22float2(*reinterpret_cast<__half2*>(&raw.z));
            float2 f3 = __half22float2(*reinterpret_cast<__half2*>(&raw.w));
            #pragma unroll
            for (int j = 0; j < 4; j++) {
                int t = r - j;
                if (t >= 0 && t < KKQ) {
                    acc[j][0] += f0.x * w[0][t]; acc[j][1] += f0.y * w[1][t];
                    acc[j][2] += f1.x * w[2][t]; acc[j][3] += f1.y * w[3][t];
                    acc[j][4] += f2.x * w[4][t]; acc[j][5] += f2.y * w[5][t];
                    acc[j][6] += f3.x * w[6][t]; acc[j][7] += f3.y * w[7][t];
                }
            }
        }
    }
    #pragma unroll
    for (int j = 0; j < 4; j++) {
        __half2 o0 = __floats2half2_rn(acc[j][0], acc[j][1]);
        __half2 o1 = __floats2half2_rn(acc[j][2], acc[j][3]);
        __half2 o2 = __floats2half2_rn(acc[j][4], acc[j][5]);
        __half2 o3 = __floats2half2_rn(acc[j][6], acc[j][7]);
        uint4 o;
        o.x = *reinterpret_cast<uint32_t*>(&o0);
        o.y = *reinterpret_cast<uint32_t*>(&o1);
        o.z = *reinterpret_cast<uint32_t*>(&o2);
        o.w = *reinterpret_cast<uint32_t*>(&o3);
        *(uint4*)&g_xh[(((size_t)b * SSQ + s0 + j) << 9) + c8] = o;
    }
}

// single fused fp32->fp16 weight conversion for all 9 matrices (float4)
__global__ void k_f2h_all(const float* __restrict__ pw_w, const float* __restrict__ wq,
                          const float* __restrict__ wk, const float* __restrict__ wv,
                          const float* __restrict__ wo, const float* __restrict__ fw) {
    const int WSZ4 = (DDQ * DDQ) / 4;
    int idx4 = blockIdx.x * 256 + threadIdx.x;
    if (idx4 >= 9 * WSZ4) return;
    int seg = idx4 / WSZ4;
    int off4 = idx4 - seg * WSZ4;
    const float* src;
    if (seg < 4)      src = pw_w + (size_t)seg * DDQ * DDQ;
    else if (seg == 4) src = wq;
    else if (seg == 5) src = wk;
    else if (seg == 6) src = wv;
    else if (seg == 7) src = wo;
    else               src = fw;
    float4 v = ((const float4*)src)[off4];
    __half2 h01 = __floats2half2_rn(v.x, v.y), h23 = __floats2half2_rn(v.z, v.w);
    uint2 o;
    o.x = *reinterpret_cast<uint32_t*>(&h01);
    o.y = *reinterpret_cast<uint32_t*>(&h23);
    *(uint2*)&g_wh[((size_t)seg * DDQ * DDQ) + off4 * 4] = o;
}

// ---------------- host orchestration -----------------------------------------
extern "C" void kernel_launch(void* const* d_in, const int* in_sizes, int n_in,
                              void* d_out, int out_size) {
    const float* x    = (const float*)d_in[0];
    const int*   mask = (const int*)  d_in[1];
    const float* dw_w = (const float*)d_in[2];
    const float* pw_w = (const float*)d_in[3];
    const float* pw_b = (const float*)d_in[4];
    const float* cg   = (const float*)d_in[5];
    const float* cb   = (const float*)d_in[6];
    const float* pg   = (const float*)d_in[7];
    const float* pb   = (const float*)d_in[8];
    const float* wq   = (const float*)d_in[9];
    const float* bq   = (const float*)d_in[10];
    const float* wk   = (const float*)d_in[11];
    const float* bk   = (const float*)d_in[12];
    const float* wv   = (const float*)d_in[13];
    const float* bv   = (const float*)d_in[14];
    const float* wo   = (const float*)d_in[15];
    const float* bo   = (const float*)d_in[16];
    const float* fg   = (const float*)d_in[17];
    const float* fb   = (const float*)d_in[18];
    const float* fw   = (const float*)d_in[19];
    const float* fbi  = (const float*)d_in[20];
    float* out = (float*)d_out;

    float* p_res;
    __half *p_xh, *p_yh, *p_wh, *p_qh, *p_qkv;
    cudaGetSymbolAddress((void**)&p_res, g_res);
    cudaGetSymbolAddress((void**)&p_xh,  g_xh);
    cudaGetSymbolAddress((void**)&p_yh,  g_yh);
    cudaGetSymbolAddress((void**)&p_wh,  g_wh);
    cudaGetSymbolAddress((void**)&p_qh,  g_qh);
    cudaGetSymbolAddress((void**)&p_qkv, g_qkv);

    cudaFuncSetAttribute(k_flash, cudaFuncAttributeMaxDynamicSharedMemorySize, FLASH_SMEM);

    const int WSZ = DDQ * DDQ;  // 262144
    dim3 dg(4, 96);             // N=512: N/128, M/64
    dim3 dg3(12, 96);           // N=1536 fused QKV

    // 0. weights -> fp16
    k_f2h_all<<<(9 * WSZ / 4 + 255) / 256, 256>>>(pw_w, wq, wk, wv, wo, fw);

    // 1. res = x + PE ; LN -> fp16 (conv input in g_qh)
    k_addpos_ln<<<MMQ, 128>>>(x, p_qh, pg, pb);

    // 2. conv stack: dwconv -> GEMM(Y fp16) -> addln (res += Y; LN)
    for (int l = 0; l < LLQ; l++) {
        k_dwconv_h<<<(MMQ / 4) * 64 / 256, 256>>>(p_qh, dw_w + l * DDQ * KKQ);
        k_gemm_h<1, 0><<<dg, 256>>>(p_xh, p_wh + (size_t)l * WSZ,
                                    pw_b + l * DDQ, nullptr, nullptr,
                                    nullptr, nullptr, p_yh);
        k_addln<<<MMQ, 128>>>(p_yh, (l < LLQ - 1) ? p_qh : p_xh,
                              cg + l * DDQ, cb + l * DDQ);
    }

    // 3. attention: fused QKV -> flash -> wo GEMM (Y fp16) -> addln (ff LN)
    k_gemm_h<0, 1><<<dg3, 256>>>(p_xh, p_wh + 4 * (size_t)WSZ,
                                 bq, bk, bv, nullptr, nullptr, p_qkv);
    k_flash<<<dim3(3, BHQ), 256, FLASH_SMEM>>>(mask);
    k_gemm_h<0, 0><<<dg, 256>>>(p_xh, p_wh + 7 * (size_t)WSZ,
                                bo, nullptr, nullptr, nullptr, nullptr, p_yh);
    k_addln<<<MMQ, 128>>>(p_yh, p_xh, fg, fb);

    // 4. feedforward final: out = relu(LN @ fw^T + fb) + res  (fp32 epilogue)
    k_gemm_h<1, 2><<<dg, 256>>>(p_xh, p_wh + 8 * (size_t)WSZ,
                                fbi, nullptr, nullptr, p_res, out, nullptr);
}

// round 14
// speedup vs baseline: 1.0584x; 1.0584x over previous
#include <cuda_runtime.h>
#include <cuda_fp16.h>
#include <math.h>
#include <stdint.h>

// Problem constants
#define BB   16
#define SSQ  384
#define DDQ  512
#define HHQ  8
#define HDQ  64
#define LLQ  4
#define KKQ  7
#define MMQ  (BB*SSQ)      // 6144 rows
#define BHQ  (BB*HHQ)      // 128 batch*heads

// ---------------- scratch (device globals; no allocation allowed) -----------
__device__ float g_res[MMQ*DDQ];                        // fp32 residual spine
__device__ __half g_xh[MMQ*DDQ];                        // fp16 GEMM A operand
__device__ __half g_yh[MMQ*DDQ];                        // fp16 GEMM Y output
__device__ __half g_wh[9*DDQ*DDQ];                      // fp16 weights
__device__ __half g_qh[MMQ*DDQ];                        // LN16 out (conv input)
__device__ __half g_qkv[3*MMQ*DDQ];                     // fused QKV, head-major

// ================= low-level helpers =========================================
__device__ __forceinline__ uint32_t smem_u32(const void* p) {
    uint32_t a;
    asm("{ .reg .u64 t; cvta.to.shared.u64 t, %1; cvt.u32.u64 %0, t; }" : "=r"(a) : "l"(p));
    return a;
}
__device__ __forceinline__ void cpa16(uint32_t dst, const void* src) {
    asm volatile("cp.async.cg.shared.global [%0], [%1], 16;" :: "r"(dst), "l"(src) : "memory");
}
#define CP_COMMIT() asm volatile("cp.async.commit_group;" ::: "memory")
#define CP_WAIT(n)  asm volatile("cp.async.wait_group %0;" :: "n"(n) : "memory")

__device__ __forceinline__ void ldsm4(uint32_t* r, uint32_t addr) {
    asm volatile("ldmatrix.sync.aligned.m8n8.x4.shared.b16 {%0,%1,%2,%3}, [%4];"
                 : "=r"(r[0]), "=r"(r[1]), "=r"(r[2]), "=r"(r[3]) : "r"(addr));
}
__device__ __forceinline__ void ldsm4t(uint32_t* r, uint32_t addr) {
    asm volatile("ldmatrix.sync.aligned.m8n8.x4.trans.shared.b16 {%0,%1,%2,%3}, [%4];"
                 : "=r"(r[0]), "=r"(r[1]), "=r"(r[2]), "=r"(r[3]) : "r"(addr));
}
__device__ __forceinline__ void hmma(float* d, const uint32_t* a, uint32_t b0, uint32_t b1) {
    asm volatile(
        "mma.sync.aligned.m16n8k16.row.col.f32.f16.f16.f32 "
        "{%0,%1,%2,%3}, {%4,%5,%6,%7}, {%8,%9}, {%0,%1,%2,%3};"
        : "+f"(d[0]), "+f"(d[1]), "+f"(d[2]), "+f"(d[3])
        : "r"(a[0]), "r"(a[1]), "r"(a[2]), "r"(a[3]), "r"(b0), "r"(b1));
}
__device__ __forceinline__ uint32_t packh2(float x, float y) {
    __half2 h = __floats2half2_rn(x, y);
    return *reinterpret_cast<uint32_t*>(&h);
}

// ================= dense GEMM: Y[6144,N] = X@W^T + epilogue ==================
// X fp16 [M,512], W fp16 [N,512]. BM=64 BN=128 BK=64, 256 threads
// (8 warps, 2m x 4n, warp tile 32x32), cp.async 3-stage, 3 blocks/SM.
// MODE 0: Y fp16 (bias+optional relu)   MODE 1: fused QKV scatter   MODE 2: fp32 +res
template<int RELU, int MODE>
__global__ void __launch_bounds__(256, 3)
k_gemm_h(const __half* __restrict__ X, const __half* __restrict__ W,
         const float* __restrict__ bias, const float* __restrict__ bias2,
         const float* __restrict__ bias3, const float* __restrict__ res,
         float* __restrict__ outf, __half* __restrict__ outh) {
    __shared__ __half As[3][64 * 64];
    __shared__ __half Bs[3][128 * 64];
    const int tid = threadIdx.x, lane = tid & 31, wid = tid >> 5;
    const int wm = wid >> 2, wn = wid & 3;
    const int m0 = blockIdx.y * 64, n0 = blockIdx.x * 128;
    float acc[2][4][4] = {};

    const uint32_t aB[3] = { smem_u32(&As[0][0]), smem_u32(&As[1][0]), smem_u32(&As[2][0]) };
    const uint32_t bB[3] = { smem_u32(&Bs[0][0]), smem_u32(&Bs[1][0]), smem_u32(&Bs[2][0]) };

    auto load_stage = [&](int kt, int st) {
        #pragma unroll
        for (int i = 0; i < 2; i++) {
            int q = tid + i * 256; int r = q >> 3, c = q & 7;
            cpa16(aB[st] + r * 128 + ((c ^ (r & 7)) * 16),
                  X + (size_t)(m0 + r) * DDQ + kt * 64 + c * 8);
        }
        #pragma unroll
        for (int i = 0; i < 4; i++) {
            int q = tid + i * 256; int r = q >> 3, c = q & 7;
            cpa16(bB[st] + r * 128 + ((c ^ (r & 7)) * 16),
                  W + (size_t)(n0 + r) * DDQ + kt * 64 + c * 8);
        }
        CP_COMMIT();
    };

    load_stage(0, 0);
    load_stage(1, 1);

    #pragma unroll 1
    for (int kt = 0; kt < 8; kt++) {
        int st = kt % 3;
        if (kt < 7) { CP_WAIT(1); } else { CP_WAIT(0); }
        __syncthreads();
        if (kt + 2 < 8) load_stage(kt + 2, (kt + 2) % 3);

        #pragma unroll
        for (int ks = 0; ks < 4; ks++) {
            uint32_t a[2][4], bfr[2][4];
            #pragma unroll
            for (int mt = 0; mt < 2; mt++) {
                int r = wm * 32 + mt * 16 + (lane & 15);
                int c = ks * 2 + (lane >> 4);
                ldsm4(a[mt], aB[st] + r * 128 + ((c ^ (r & 7)) * 16));
            }
            #pragma unroll
            for (int np = 0; np < 2; np++) {
                int nr = wn * 32 + np * 16 + (lane & 7) + ((lane >> 4) << 3);
                int c = ks * 2 + ((lane >> 3) & 1);
                ldsm4(bfr[np], bB[st] + nr * 128 + ((c ^ (nr & 7)) * 16));
            }
            #pragma unroll
            for (int mt = 0; mt < 2; mt++)
                #pragma unroll
                for (int nt = 0; nt < 4; nt++)
                    hmma(acc[mt][nt], a[mt],
                         bfr[nt >> 1][(nt & 1) * 2], bfr[nt >> 1][(nt & 1) * 2 + 1]);
        }
    }

    // epilogue
    const int mat = n0 >> 9;
    const int col0 = n0 & 511;
    const float* bp = (MODE == 1) ? ((mat == 0) ? bias : ((mat == 1) ? bias2 : bias3)) : bias;
    __half* ob = (MODE == 1) ? (outh + (size_t)mat * MMQ * DDQ) : outh;
    #pragma unroll
    for (int mt = 0; mt < 2; mt++) {
        int r = m0 + wm * 32 + mt * 16 + (lane >> 2);
        #pragma unroll
        for (int nt = 0; nt < 4; nt++) {
            int cl = wn * 32 + nt * 8 + (lane & 3) * 2;
            int col = (MODE == 1) ? (col0 + cl) : 0;
            int n = n0 + cl;
            float b0, b1;
            if (MODE == 1) { b0 = bp[col]; b1 = bp[col + 1]; }
            else           { b0 = bp[n];   b1 = bp[n + 1]; }
            float v00 = acc[mt][nt][0] + b0, v01 = acc[mt][nt][1] + b1;
            float v10 = acc[mt][nt][2] + b0, v11 = acc[mt][nt][3] + b1;
            if (RELU) {
                v00 = fmaxf(v00, 0.f); v01 = fmaxf(v01, 0.f);
                v10 = fmaxf(v10, 0.f); v11 = fmaxf(v11, 0.f);
            }
            if (MODE == 0) {
                *(__half2*)&ob[(size_t)r * DDQ + n] = __floats2half2_rn(v00, v01);
                *(__half2*)&ob[(size_t)(r + 8) * DDQ + n] = __floats2half2_rn(v10, v11);
            } else if (MODE == 1) {
                int h = col >> 6, hd = col & 63;
                int b_ = r / SSQ, s = r % SSQ;
                *(__half2*)&ob[(((size_t)(b_ * HHQ + h) * SSQ + s) << 6) + hd] =
                    __floats2half2_rn(v00, v01);
                int b2 = (r + 8) / SSQ, s2 = (r + 8) % SSQ;
                *(__half2*)&ob[(((size_t)(b2 * HHQ + h) * SSQ + s2) << 6) + hd] =
                    __floats2half2_rn(v10, v11);
            } else {
                float2 r0 = *(const float2*)&res[(size_t)r * DDQ + n];
                float2 r1 = *(const float2*)&res[(size_t)(r + 8) * DDQ + n];
                *(float2*)&outf[(size_t)r * DDQ + n] = make_float2(v00 + r0.x, v01 + r0.y);
                *(float2*)&outf[(size_t)(r + 8) * DDQ + n] = make_float2(v10 + r1.x, v11 + r1.y);
            }
        }
    }
}

// ================= flash attention ==========================================
__global__ void __launch_bounds__(256)
k_flash(const int* __restrict__ mask) {
    __shared__ __half Qs[128 * 64];
    __shared__ __half Ks[128 * 64];
    __shared__ __half Vs[128 * 64];
    __shared__ int misk[SSQ];
    const int bh = blockIdx.y, b = bh >> 3, h = bh & 7;
    const __half* Q = g_qkv + (size_t)bh * SSQ * HDQ;
    const __half* K = g_qkv + (size_t)MMQ * DDQ + (size_t)bh * SSQ * HDQ;
    const __half* V = g_qkv + 2 * (size_t)MMQ * DDQ + (size_t)bh * SSQ * HDQ;
    const int m0 = blockIdx.x * 128;
    const int tid = threadIdx.x, lane = tid & 31, w = tid >> 5;
    const uint32_t qB = smem_u32(Qs), kB = smem_u32(Ks), vB = smem_u32(Vs);

    // mask: load all 384 once
    for (int i = tid; i < SSQ; i += 256) misk[i] = mask[b * SSQ + i];

    #pragma unroll
    for (int i = 0; i < 4; i++) {
        int q = tid + i * 256; int r = q >> 3, c = q & 7;
        cpa16(qB + r * 128 + ((c ^ (r & 7)) * 16), Q + (size_t)(m0 + r) * HDQ + c * 8);
    }

    float o[8][4] = {};
    float mrow0 = -3.0e38f, mrow1 = -3.0e38f, lrow0 = 0.f, lrow1 = 0.f;
    const float LOG2E = 1.4426950408889634f;

    #pragma unroll 1
    for (int kc = 0; kc < 3; kc++) {
        #pragma unroll
        for (int i = 0; i < 4; i++) {
            int q = tid + i * 256; int r = q >> 3, c = q & 7;
            cpa16(kB + r * 128 + ((c ^ (r & 7)) * 16),
                  K + (size_t)(kc * 128 + r) * HDQ + c * 8);
            cpa16(vB + r * 128 + ((c ^ (r & 7)) * 16),
                  V + (size_t)(kc * 128 + r) * HDQ + c * 8);
        }
        CP_COMMIT(); CP_WAIT(0);
        __syncthreads();

        float s[16][4] = {};
        #pragma unroll
        for (int ks = 0; ks < 4; ks++) {
            uint32_t a[4];
            { int r = w * 16 + (lane & 15);
              int c = ks * 2 + (lane >> 4);
              ldsm4(a, qB + r * 128 + ((c ^ (r & 7)) * 16)); }
            #pragma unroll
            for (int np = 0; np < 8; np++) {
                uint32_t bf[4];
                int nr = np * 16 + (lane & 7) + ((lane >> 4) << 3);
                int c = ks * 2 + ((lane >> 3) & 1);
                ldsm4(bf, kB + nr * 128 + ((c ^ (nr & 7)) * 16));
                hmma(s[np * 2 + 0], a, bf[0], bf[1]);
                hmma(s[np * 2 + 1], a, bf[2], bf[3]);
            }
        }

        float mx0 = -3.0e38f, mx1 = -3.0e38f;
        #pragma unroll
        for (int nt = 0; nt < 16; nt++) {
            int nc = kc * 128 + nt * 8 + (lane & 3) * 2;
            int f0 = misk[nc], f1 = misk[nc + 1];
            s[nt][0] = f0 ? -1e10f : s[nt][0] * 0.125f;
            s[nt][1] = f1 ? -1e10f : s[nt][1] * 0.125f;
            s[nt][2] = f0 ? -1e10f : s[nt][2] * 0.125f;
            s[nt][3] = f1 ? -1e10f : s[nt][3] * 0.125f;
            mx0 = fmaxf(mx0, fmaxf(s[nt][0], s[nt][1]));
            mx1 = fmaxf(mx1, fmaxf(s[nt][2], s[nt][3]));
        }
        #pragma unroll
        for (int of = 1; of <= 2; of <<= 1) {
            mx0 = fmaxf(mx0, __shfl_xor_sync(0xffffffffu, mx0, of));
            mx1 = fmaxf(mx1, __shfl_xor_sync(0xffffffffu, mx1, of));
        }
        float mn0 = fmaxf(mrow0, mx0), mn1 = fmaxf(mrow1, mx1);
        float al0 = exp2f((mrow0 - mn0) * LOG2E);
        float al1 = exp2f((mrow1 - mn1) * LOG2E);
        mrow0 = mn0; mrow1 = mn1;

        float sum0 = 0.f, sum1 = 0.f;
        #pragma unroll
        for (int nt = 0; nt < 16; nt++) {
            s[nt][0] = exp2f((s[nt][0] - mn0) * LOG2E);
            s[nt][1] = exp2f((s[nt][1] - mn0) * LOG2E);
            s[nt][2] = exp2f((s[nt][2] - mn1) * LOG2E);
            s[nt][3] = exp2f((s[nt][3] - mn1) * LOG2E);
            sum0 += s[nt][0] + s[nt][1];
            sum1 += s[nt][2] + s[nt][3];
        }
        #pragma unroll
        for (int of = 1; of <= 2; of <<= 1) {
            sum0 += __shfl_xor_sync(0xffffffffu, sum0, of);
            sum1 += __shfl_xor_sync(0xffffffffu, sum1, of);
        }
        lrow0 = lrow0 * al0 + sum0;
        lrow1 = lrow1 * al1 + sum1;

        #pragma unroll
        for (int t = 0; t < 8; t++) {
            o[t][0] *= al0; o[t][1] *= al0; o[t][2] *= al1; o[t][3] *= al1;
        }

        #pragma unroll
        for (int kg = 0; kg < 8; kg++) {
            uint32_t a[4];
            a[0] = packh2(s[kg * 2][0],     s[kg * 2][1]);
            a[1] = packh2(s[kg * 2][2],     s[kg * 2][3]);
            a[2] = packh2(s[kg * 2 + 1][0], s[kg * 2 + 1][1]);
            a[3] = packh2(s[kg * 2 + 1][2], s[kg * 2 + 1][3]);
            #pragma unroll
            for (int vn = 0; vn < 4; vn++) {
                uint32_t bf[4];
                int row = kg * 16 + (lane & 7) + ((lane >> 3) & 1) * 8;
                int c = vn * 2 + (lane >> 4);
                ldsm4t(bf, vB + row * 128 + ((c ^ (row & 7)) * 16));
                hmma(o[vn * 2 + 0], a, bf[0], bf[1]);
                hmma(o[vn * 2 + 1], a, bf[2], bf[3]);
            }
        }
        __syncthreads();
    }

    float inv0 = 1.f / lrow0, inv1 = 1.f / lrow1;
    int m = m0 + w * 16 + (lane >> 2);
    #pragma unroll
    for (int t = 0; t < 8; t++) {
        int hd = t * 8 + (lane & 3) * 2;
        *(__half2*)&g_xh[((size_t)(b * SSQ + m)) * DDQ + h * HDQ + hd] =
            __floats2half2_rn(o[t][0] * inv0, o[t][1] * inv0);
        *(__half2*)&g_xh[((size_t)(b * SSQ + m + 8)) * DDQ + h * HDQ + hd] =
            __floats2half2_rn(o[t][2] * inv1, o[t][3] * inv1);
    }
}

// ================= elementwise / reduction kernels ===========================
__inline__ __device__ float blockReduceSum128(float val) {
    __shared__ float sh[4];
    int lane = threadIdx.x & 31, w = threadIdx.x >> 5;
    #pragma unroll
    for (int o = 16; o; o >>= 1) val += __shfl_xor_sync(0xffffffffu, val, o);
    if (lane == 0) sh[w] = val;
    __syncthreads();
    float r = sh[0] + sh[1] + sh[2] + sh[3];
    __syncthreads();
    return r;
}

// fused: res = x + PE; tgt(fp16) = LN(res)*g + b.  one block (128 thr) per row.
__global__ void k_addpos_ln(const float* __restrict__ x, __half* __restrict__ tgt,
                            const float* __restrict__ gm, const float* __restrict__ bt) {
    int row = blockIdx.x;
    int s = row % SSQ;
    int t = threadIdx.x;
    int c = t * 4;
    float4 v = ((const float4*)(x + (size_t)row * DDQ))[t];
    float pe[4];
    #pragma unroll
    for (int i = 0; i < 4; i++) {
        int ci = c + i;
        float inv = exp2f(-((float)(2 * ci) * (1.0f / 512.0f)) * 13.2877123795494f);
        float ang = (float)s * inv;
        pe[i] = (ci & 1) ? cosf(ang) : sinf(ang);
    }
    v.x += pe[0]; v.y += pe[1]; v.z += pe[2]; v.w += pe[3];
    ((float4*)(g_res + (size_t)row * DDQ))[t] = v;

    float sm = v.x + v.y + v.z + v.w;
    float mean = blockReduceSum128(sm) * (1.0f / DDQ);
    float dx = v.x - mean, dy = v.y - mean, dz = v.z - mean, dw = v.w - mean;
    float s2 = dx*dx + dy*dy + dz*dz + dw*dw;
    float var = blockReduceSum128(s2) * (1.0f / DDQ);
    float inv = rsqrtf(var + 1e-5f);
    float ox = dx * inv * gm[c+0] + bt[c+0];
    float oy = dy * inv * gm[c+1] + bt[c+1];
    float oz = dz * inv * gm[c+2] + bt[c+2];
    float ow = dw * inv * gm[c+3] + bt[c+3];
    __half2* hp = (__half2*)(tgt + (size_t)row * DDQ + c);
    hp[0] = __floats2half2_rn(ox, oy);
    hp[1] = __floats2half2_rn(oz, ow);
}

// fused: res += Y(fp16); tgt(fp16) = LN(res)*g + b.  one block (128 thr) per row.
__global__ void k_addln(const __half* __restrict__ y, __half* __restrict__ tgt,
                        const float* __restrict__ gm, const float* __restrict__ bt) {
    int row = blockIdx.x;
    int t = threadIdx.x;
    int c = t * 4;
    float4 v = ((const float4*)(g_res + (size_t)row * DDQ))[t];
    uint2 raw = *(const uint2*)&y[(size_t)row * DDQ + c];
    __half2 y01 = *reinterpret_cast<__half2*>(&raw.x);
    __half2 y23 = *reinterpret_cast<__half2*>(&raw.y);
    float2 f01 = __half22float2(y01), f23 = __half22float2(y23);
    v.x += f01.x; v.y += f01.y; v.z += f23.x; v.w += f23.y;
    ((float4*)(g_res + (size_t)row * DDQ))[t] = v;

    float sm = v.x + v.y + v.z + v.w;
    float mean = blockReduceSum128(sm) * (1.0f / DDQ);
    float dx = v.x - mean, dy = v.y - mean, dz = v.z - mean, dw = v.w - mean;
    float s2 = dx*dx + dy*dy + dz*dz + dw*dw;
    float var = blockReduceSum128(s2) * (1.0f / DDQ);
    float inv = rsqrtf(var + 1e-5f);
    float ox = dx * inv * gm[c+0] + bt[c+0];
    float oy = dy * inv * gm[c+1] + bt[c+1];
    float oz = dz * inv * gm[c+2] + bt[c+2];
    float ow = dw * inv * gm[c+3] + bt[c+3];
    __half2* hp = (__half2*)(tgt + (size_t)row * DDQ + c);
    hp[0] = __floats2half2_rn(ox, oy);
    hp[1] = __floats2half2_rn(oz, ow);
}

// depthwise conv (K=7, same padding), fp16 in/out.
// thread = 4 channels x 4 consecutive s positions (10 row-loads / 16 outputs).
__global__ void __launch_bounds__(256)
k_dwconv_h(const __half* __restrict__ in, const float* __restrict__ dw) {
    int idx = blockIdx.x * 256 + threadIdx.x;
    if (idx >= (MMQ / 4) * 128) return;
    int c4 = (idx & 127) * 4;
    int bs4 = idx >> 7;
    const int SC = SSQ / 4;
    int b = bs4 / SC, s0 = (bs4 - b * SC) * 4;

    float w[4][KKQ];
    #pragma unroll
    for (int i = 0; i < 4; i++)
        #pragma unroll
        for (int k = 0; k < KKQ; k++)
            w[i][k] = dw[(c4 + i) * KKQ + k];

    float acc[4][4] = {};
    #pragma unroll
    for (int r = 0; r < 10; r++) {
        int ss = s0 - 3 + r;
        if (ss >= 0 && ss < SSQ) {
            uint2 raw = *(const uint2*)&in[(((size_t)b * SSQ + ss) << 9) + c4];
            __half2 h01 = *reinterpret_cast<__half2*>(&raw.x);
            __half2 h23 = *reinterpret_cast<__half2*>(&raw.y);
            float2 f01 = __half22float2(h01), f23 = __half22float2(h23);
            #pragma unroll
            for (int j = 0; j < 4; j++) {
                int t = r - j;
                if (t >= 0 && t < KKQ) {
                    acc[j][0] += f01.x * w[0][t];
                    acc[j][1] += f01.y * w[1][t];
                    acc[j][2] += f23.x * w[2][t];
                    acc[j][3] += f23.y * w[3][t];
                }
            }
        }
    }
    #pragma unroll
    for (int j = 0; j < 4; j++) {
        __half2 o01 = __floats2half2_rn(acc[j][0], acc[j][1]);
        __half2 o23 = __floats2half2_rn(acc[j][2], acc[j][3]);
        uint2 o;
        o.x = *reinterpret_cast<uint32_t*>(&o01);
        o.y = *reinterpret_cast<uint32_t*>(&o23);
        *(uint2*)&g_xh[(((size_t)b * SSQ + s0 + j) << 9) + c4] = o;
    }
}

// single fused fp32->fp16 weight conversion for all 9 matrices (float4)
__global__ void k_f2h_all(const float* __restrict__ pw_w, const float* __restrict__ wq,
                          const float* __restrict__ wk, const float* __restrict__ wv,
                          const float* __restrict__ wo, const float* __restrict__ fw) {
    const int WSZ4 = (DDQ * DDQ) / 4;
    int idx4 = blockIdx.x * 256 + threadIdx.x;
    if (idx4 >= 9 * WSZ4) return;
    int seg = idx4 / WSZ4;
    int off4 = idx4 - seg * WSZ4;
    const float* src;
    if (seg < 4)      src = pw_w + (size_t)seg * DDQ * DDQ;
    else if (seg == 4) src = wq;
    else if (seg == 5) src = wk;
    else if (seg == 6) src = wv;
    else if (seg == 7) src = wo;
    else               src = fw;
    float4 v = ((const float4*)src)[off4];
    __half2 h01 = __floats2half2_rn(v.x, v.y), h23 = __floats2half2_rn(v.z, v.w);
    uint2 o;
    o.x = *reinterpret_cast<uint32_t*>(&h01);
    o.y = *reinterpret_cast<uint32_t*>(&h23);
    *(uint2*)&g_wh[((size_t)seg * DDQ * DDQ) + off4 * 4] = o;
}

// ---------------- host orchestration -----------------------------------------
extern "C" void kernel_launch(void* const* d_in, const int* in_sizes, int n_in,
                              void* d_out, int out_size) {
    const float* x    = (const float*)d_in[0];
    const int*   mask = (const int*)  d_in[1];
    const float* dw_w = (const float*)d_in[2];
    const float* pw_w = (const float*)d_in[3];
    const float* pw_b = (const float*)d_in[4];
    const float* cg   = (const float*)d_in[5];
    const float* cb   = (const float*)d_in[6];
    const float* pg   = (const float*)d_in[7];
    const float* pb   = (const float*)d_in[8];
    const float* wq   = (const float*)d_in[9];
    const float* bq   = (const float*)d_in[10];
    const float* wk   = (const float*)d_in[11];
    const float* bk   = (const float*)d_in[12];
    const float* wv   = (const float*)d_in[13];
    const float* bv   = (const float*)d_in[14];
    const float* wo   = (const float*)d_in[15];
    const float* bo   = (const float*)d_in[16];
    const float* fg   = (const float*)d_in[17];
    const float* fb   = (const float*)d_in[18];
    const float* fw   = (const float*)d_in[19];
    const float* fbi  = (const float*)d_in[20];
    float* out = (float*)d_out;

    float* p_res;
    __half *p_xh, *p_yh, *p_wh, *p_qh, *p_qkv;
    cudaGetSymbolAddress((void**)&p_res, g_res);
    cudaGetSymbolAddress((void**)&p_xh,  g_xh);
    cudaGetSymbolAddress((void**)&p_yh,  g_yh);
    cudaGetSymbolAddress((void**)&p_wh,  g_wh);
    cudaGetSymbolAddress((void**)&p_qh,  g_qh);
    cudaGetSymbolAddress((void**)&p_qkv, g_qkv);

    const int WSZ = DDQ * DDQ;  // 262144
    dim3 dg(4, 96);             // N=512: N/128, M/64
    dim3 dg3(12, 96);           // N=1536 fused QKV

    // 0. weights -> fp16
    k_f2h_all<<<(9 * WSZ / 4 + 255) / 256, 256>>>(pw_w, wq, wk, wv, wo, fw);

    // 1. res = x + PE ; LN -> fp16 (conv input in g_qh)
    k_addpos_ln<<<MMQ, 128>>>(x, p_qh, pg, pb);

    // 2. conv stack: dwconv -> GEMM(Y fp16) -> addln (res += Y; LN)
    for (int l = 0; l < LLQ; l++) {
        k_dwconv_h<<<(MMQ / 4) * 128 / 256, 256>>>(p_qh, dw_w + l * DDQ * KKQ);
        k_gemm_h<1, 0><<<dg, 256>>>(p_xh, p_wh + (size_t)l * WSZ,
                                    pw_b + l * DDQ, nullptr, nullptr,
                                    nullptr, nullptr, p_yh);
        k_addln<<<MMQ, 128>>>(p_yh, (l < LLQ - 1) ? p_qh : p_xh,
                              cg + l * DDQ, cb + l * DDQ);
    }

    // 3. attention: fused QKV -> flash -> wo GEMM (Y fp16) -> addln (ff LN)
    k_gemm_h<0, 1><<<dg3, 256>>>(p_xh, p_wh + 4 * (size_t)WSZ,
                                 bq, bk, bv, nullptr, nullptr, p_qkv);
    k_flash<<<dim3(3, BHQ), 256>>>(mask);
    k_gemm_h<0, 0><<<dg, 256>>>(p_xh, p_wh + 7 * (size_t)WSZ,
                                bo, nullptr, nullptr, nullptr, nullptr, p_yh);
    k_addln<<<MMQ, 128>>>(p_yh, p_xh, fg, fb);

    // 4. feedforward final: out = relu(LN @ fw^T + fb) + res  (fp32 epilogue)
    k_gemm_h<1, 2><<<dg, 256>>>(p_xh, p_wh + 8 * (size_t)WSZ,
                                fbi, nullptr, nullptr, p_res, out, nullptr);
}

// round 15
// speedup vs baseline: 1.0765x; 1.0171x over previous
#include <cuda_runtime.h>
#include <cuda_fp16.h>
#include <math.h>
#include <stdint.h>

// Problem constants
#define BB   16
#define SSQ  384
#define DDQ  512
#define HHQ  8
#define HDQ  64
#define LLQ  4
#define KKQ  7
#define MMQ  (BB*SSQ)      // 6144 rows
#define BHQ  (BB*HHQ)      // 128 batch*heads

// ---------------- scratch (device globals; no allocation allowed) -----------
__device__ float g_res[MMQ*DDQ];                        // fp32 residual spine
__device__ __half g_xh[MMQ*DDQ];                        // fp16 GEMM A operand
__device__ __half g_yh[MMQ*DDQ];                        // fp16 GEMM Y output
__device__ __half g_wh[9*DDQ*DDQ];                      // fp16 weights
__device__ __half g_qh[MMQ*DDQ];                        // LN16 out (conv input)
__device__ __half g_qkv[3*MMQ*DDQ];                     // fused QKV, head-major

// ================= low-level helpers =========================================
__device__ __forceinline__ uint32_t smem_u32(const void* p) {
    uint32_t a;
    asm("{ .reg .u64 t; cvta.to.shared.u64 t, %1; cvt.u32.u64 %0, t; }" : "=r"(a) : "l"(p));
    return a;
}
__device__ __forceinline__ void cpa16(uint32_t dst, const void* src) {
    asm volatile("cp.async.cg.shared.global [%0], [%1], 16;" :: "r"(dst), "l"(src) : "memory");
}
#define CP_COMMIT() asm volatile("cp.async.commit_group;" ::: "memory")
#define CP_WAIT(n)  asm volatile("cp.async.wait_group %0;" :: "n"(n) : "memory")

__device__ __forceinline__ void ldsm4(uint32_t* r, uint32_t addr) {
    asm volatile("ldmatrix.sync.aligned.m8n8.x4.shared.b16 {%0,%1,%2,%3}, [%4];"
                 : "=r"(r[0]), "=r"(r[1]), "=r"(r[2]), "=r"(r[3]) : "r"(addr));
}
__device__ __forceinline__ void ldsm4t(uint32_t* r, uint32_t addr) {
    asm volatile("ldmatrix.sync.aligned.m8n8.x4.trans.shared.b16 {%0,%1,%2,%3}, [%4];"
                 : "=r"(r[0]), "=r"(r[1]), "=r"(r[2]), "=r"(r[3]) : "r"(addr));
}
__device__ __forceinline__ void hmma(float* d, const uint32_t* a, uint32_t b0, uint32_t b1) {
    asm volatile(
        "mma.sync.aligned.m16n8k16.row.col.f32.f16.f16.f32 "
        "{%0,%1,%2,%3}, {%4,%5,%6,%7}, {%8,%9}, {%0,%1,%2,%3};"
        : "+f"(d[0]), "+f"(d[1]), "+f"(d[2]), "+f"(d[3])
        : "r"(a[0]), "r"(a[1]), "r"(a[2]), "r"(a[3]), "r"(b0), "r"(b1));
}
__device__ __forceinline__ uint32_t packh2(float x, float y) {
    __half2 h = __floats2half2_rn(x, y);
    return *reinterpret_cast<uint32_t*>(&h);
}

// ================= dense GEMM (N=512 layers): BM=64 BN=128 BK=64 =============
// 256 threads (8 warps, 2m x 4n, warp tile 32x32), cp.async 3-stage, 3 blk/SM.
// MODE 0: Y fp16 (bias+optional relu)   MODE 2: fp32 +res (final FF layer)
template<int RELU, int MODE>
__global__ void __launch_bounds__(256, 3)
k_gemm_h(const __half* __restrict__ X, const __half* __restrict__ W,
         const float* __restrict__ bias, const float* __restrict__ res,
         float* __restrict__ outf, __half* __restrict__ outh) {
    __shared__ __half As[3][64 * 64];
    __shared__ __half Bs[3][128 * 64];
    const int tid = threadIdx.x, lane = tid & 31, wid = tid >> 5;
    const int wm = wid >> 2, wn = wid & 3;
    const int m0 = blockIdx.y * 64, n0 = blockIdx.x * 128;
    float acc[2][4][4] = {};

    const uint32_t aB[3] = { smem_u32(&As[0][0]), smem_u32(&As[1][0]), smem_u32(&As[2][0]) };
    const uint32_t bB[3] = { smem_u32(&Bs[0][0]), smem_u32(&Bs[1][0]), smem_u32(&Bs[2][0]) };

    auto load_stage = [&](int kt, int st) {
        #pragma unroll
        for (int i = 0; i < 2; i++) {
            int q = tid + i * 256; int r = q >> 3, c = q & 7;
            cpa16(aB[st] + r * 128 + ((c ^ (r & 7)) * 16),
                  X + (size_t)(m0 + r) * DDQ + kt * 64 + c * 8);
        }
        #pragma unroll
        for (int i = 0; i < 4; i++) {
            int q = tid + i * 256; int r = q >> 3, c = q & 7;
            cpa16(bB[st] + r * 128 + ((c ^ (r & 7)) * 16),
                  W + (size_t)(n0 + r) * DDQ + kt * 64 + c * 8);
        }
        CP_COMMIT();
    };

    load_stage(0, 0);
    load_stage(1, 1);

    #pragma unroll 1
    for (int kt = 0; kt < 8; kt++) {
        int st = kt % 3;
        if (kt < 7) { CP_WAIT(1); } else { CP_WAIT(0); }
        __syncthreads();
        if (kt + 2 < 8) load_stage(kt + 2, (kt + 2) % 3);

        #pragma unroll
        for (int ks = 0; ks < 4; ks++) {
            uint32_t a[2][4], bfr[2][4];
            #pragma unroll
            for (int mt = 0; mt < 2; mt++) {
                int r = wm * 32 + mt * 16 + (lane & 15);
                int c = ks * 2 + (lane >> 4);
                ldsm4(a[mt], aB[st] + r * 128 + ((c ^ (r & 7)) * 16));
            }
            #pragma unroll
            for (int np = 0; np < 2; np++) {
                int nr = wn * 32 + np * 16 + (lane & 7) + ((lane >> 4) << 3);
                int c = ks * 2 + ((lane >> 3) & 1);
                ldsm4(bfr[np], bB[st] + nr * 128 + ((c ^ (nr & 7)) * 16));
            }
            #pragma unroll
            for (int mt = 0; mt < 2; mt++)
                #pragma unroll
                for (int nt = 0; nt < 4; nt++)
                    hmma(acc[mt][nt], a[mt],
                         bfr[nt >> 1][(nt & 1) * 2], bfr[nt >> 1][(nt & 1) * 2 + 1]);
        }
    }

    // epilogue
    #pragma unroll
    for (int mt = 0; mt < 2; mt++) {
        int r = m0 + wm * 32 + mt * 16 + (lane >> 2);
        #pragma unroll
        for (int nt = 0; nt < 4; nt++) {
            int cl = wn * 32 + nt * 8 + (lane & 3) * 2;
            int n = n0 + cl;
            float b0 = bias[n], b1 = bias[n + 1];
            float v00 = acc[mt][nt][0] + b0, v01 = acc[mt][nt][1] + b1;
            float v10 = acc[mt][nt][2] + b0, v11 = acc[mt][nt][3] + b1;
            if (RELU) {
                v00 = fmaxf(v00, 0.f); v01 = fmaxf(v01, 0.f);
                v10 = fmaxf(v10, 0.f); v11 = fmaxf(v11, 0.f);
            }
            if (MODE == 0) {
                *(__half2*)&outh[(size_t)r * DDQ + n] = __floats2half2_rn(v00, v01);
                *(__half2*)&outh[(size_t)(r + 8) * DDQ + n] = __floats2half2_rn(v10, v11);
            } else {
                float2 r0 = *(const float2*)&res[(size_t)r * DDQ + n];
                float2 r1 = *(const float2*)&res[(size_t)(r + 8) * DDQ + n];
                *(float2*)&outf[(size_t)r * DDQ + n] = make_float2(v00 + r0.x, v01 + r0.y);
                *(float2*)&outf[(size_t)(r + 8) * DDQ + n] = make_float2(v10 + r1.x, v11 + r1.y);
            }
        }
    }
}

// ================= QKV GEMM (N=1536): BM=128 BN=128 BK=64 ====================
// 256 threads (8 warps, 4m x 2n, warp tile 32x64), cp.async 3-stage, 2 blk/SM.
// grid (12,48) = 576 blocks = 1.95 waves of 296 slots (near-perfect packing).
__global__ void __launch_bounds__(256, 2)
k_gemm_qkv(const __half* __restrict__ X, const __half* __restrict__ W,
           const float* __restrict__ bias, const float* __restrict__ bias2,
           const float* __restrict__ bias3, __half* __restrict__ outh) {
    __shared__ __half As[3][128 * 64];
    __shared__ __half Bs[3][128 * 64];
    const int tid = threadIdx.x, lane = tid & 31, wid = tid >> 5;
    const int wm = wid >> 1, wn = wid & 1;
    const int m0 = blockIdx.y * 128, n0 = blockIdx.x * 128;
    float acc[2][8][4] = {};

    const uint32_t aB[3] = { smem_u32(&As[0][0]), smem_u32(&As[1][0]), smem_u32(&As[2][0]) };
    const uint32_t bB[3] = { smem_u32(&Bs[0][0]), smem_u32(&Bs[1][0]), smem_u32(&Bs[2][0]) };

    auto load_stage = [&](int kt, int st) {
        #pragma unroll
        for (int i = 0; i < 4; i++) {
            int q = tid + i * 256; int r = q >> 3, c = q & 7;
            cpa16(aB[st] + r * 128 + ((c ^ (r & 7)) * 16),
                  X + (size_t)(m0 + r) * DDQ + kt * 64 + c * 8);
        }
        #pragma unroll
        for (int i = 0; i < 4; i++) {
            int q = tid + i * 256; int r = q >> 3, c = q & 7;
            cpa16(bB[st] + r * 128 + ((c ^ (r & 7)) * 16),
                  W + (size_t)(n0 + r) * DDQ + kt * 64 + c * 8);
        }
        CP_COMMIT();
    };

    load_stage(0, 0);
    load_stage(1, 1);

    #pragma unroll 1
    for (int kt = 0; kt < 8; kt++) {
        int st = kt % 3;
        if (kt < 7) { CP_WAIT(1); } else { CP_WAIT(0); }
        __syncthreads();
        if (kt + 2 < 8) load_stage(kt + 2, (kt + 2) % 3);

        #pragma unroll
        for (int ks = 0; ks < 4; ks++) {
            uint32_t a[2][4], bfr[4][4];
            #pragma unroll
            for (int mt = 0; mt < 2; mt++) {
                int r = wm * 32 + mt * 16 + (lane & 15);
                int c = ks * 2 + (lane >> 4);
                ldsm4(a[mt], aB[st] + r * 128 + ((c ^ (r & 7)) * 16));
            }
            #pragma unroll
            for (int np = 0; np < 4; np++) {
                int nr = wn * 64 + np * 16 + (lane & 7) + ((lane >> 4) << 3);
                int c = ks * 2 + ((lane >> 3) & 1);
                ldsm4(bfr[np], bB[st] + nr * 128 + ((c ^ (nr & 7)) * 16));
            }
            #pragma unroll
            for (int mt = 0; mt < 2; mt++)
                #pragma unroll
                for (int nt = 0; nt < 8; nt++)
                    hmma(acc[mt][nt], a[mt],
                         bfr[nt >> 1][(nt & 1) * 2], bfr[nt >> 1][(nt & 1) * 2 + 1]);
        }
    }

    // epilogue: head-major scatter with per-matrix bias
    const int mat = n0 >> 9;
    const int col0 = n0 & 511;
    const float* bp = (mat == 0) ? bias : ((mat == 1) ? bias2 : bias3);
    __half* ob = outh + (size_t)mat * MMQ * DDQ;
    #pragma unroll
    for (int mt = 0; mt < 2; mt++) {
        int r = m0 + wm * 32 + mt * 16 + (lane >> 2);
        #pragma unroll
        for (int nt = 0; nt < 8; nt++) {
            int cl = wn * 64 + nt * 8 + (lane & 3) * 2;
            int col = col0 + cl;
            float b0 = bp[col], b1 = bp[col + 1];
            float v00 = acc[mt][nt][0] + b0, v01 = acc[mt][nt][1] + b1;
            float v10 = acc[mt][nt][2] + b0, v11 = acc[mt][nt][3] + b1;
            int h = col >> 6, hd = col & 63;
            int b_ = r / SSQ, s = r % SSQ;
            *(__half2*)&ob[(((size_t)(b_ * HHQ + h) * SSQ + s) << 6) + hd] =
                __floats2half2_rn(v00, v01);
            int b2 = (r + 8) / SSQ, s2 = (r + 8) % SSQ;
            *(__half2*)&ob[(((size_t)(b2 * HHQ + h) * SSQ + s2) << 6) + hd] =
                __floats2half2_rn(v10, v11);
        }
    }
}

// ================= flash attention ==========================================
__global__ void __launch_bounds__(256)
k_flash(const int* __restrict__ mask) {
    __shared__ __half Qs[128 * 64];
    __shared__ __half Ks[128 * 64];
    __shared__ __half Vs[128 * 64];
    __shared__ int misk[SSQ];
    const int bh = blockIdx.y, b = bh >> 3, h = bh & 7;
    const __half* Q = g_qkv + (size_t)bh * SSQ * HDQ;
    const __half* K = g_qkv + (size_t)MMQ * DDQ + (size_t)bh * SSQ * HDQ;
    const __half* V = g_qkv + 2 * (size_t)MMQ * DDQ + (size_t)bh * SSQ * HDQ;
    const int m0 = blockIdx.x * 128;
    const int tid = threadIdx.x, lane = tid & 31, w = tid >> 5;
    const uint32_t qB = smem_u32(Qs), kB = smem_u32(Ks), vB = smem_u32(Vs);

    for (int i = tid; i < SSQ; i += 256) misk[i] = mask[b * SSQ + i];

    #pragma unroll
    for (int i = 0; i < 4; i++) {
        int q = tid + i * 256; int r = q >> 3, c = q & 7;
        cpa16(qB + r * 128 + ((c ^ (r & 7)) * 16), Q + (size_t)(m0 + r) * HDQ + c * 8);
    }

    float o[8][4] = {};
    float mrow0 = -3.0e38f, mrow1 = -3.0e38f, lrow0 = 0.f, lrow1 = 0.f;
    const float LOG2E = 1.4426950408889634f;

    #pragma unroll 1
    for (int kc = 0; kc < 3; kc++) {
        #pragma unroll
        for (int i = 0; i < 4; i++) {
            int q = tid + i * 256; int r = q >> 3, c = q & 7;
            cpa16(kB + r * 128 + ((c ^ (r & 7)) * 16),
                  K + (size_t)(kc * 128 + r) * HDQ + c * 8);
            cpa16(vB + r * 128 + ((c ^ (r & 7)) * 16),
                  V + (size_t)(kc * 128 + r) * HDQ + c * 8);
        }
        CP_COMMIT(); CP_WAIT(0);
        __syncthreads();

        float s[16][4] = {};
        #pragma unroll
        for (int ks = 0; ks < 4; ks++) {
            uint32_t a[4];
            { int r = w * 16 + (lane & 15);
              int c = ks * 2 + (lane >> 4);
              ldsm4(a, qB + r * 128 + ((c ^ (r & 7)) * 16)); }
            #pragma unroll
            for (int np = 0; np < 8; np++) {
                uint32_t bf[4];
                int nr = np * 16 + (lane & 7) + ((lane >> 4) << 3);
                int c = ks * 2 + ((lane >> 3) & 1);
                ldsm4(bf, kB + nr * 128 + ((c ^ (nr & 7)) * 16));
                hmma(s[np * 2 + 0], a, bf[0], bf[1]);
                hmma(s[np * 2 + 1], a, bf[2], bf[3]);
            }
        }

        float mx0 = -3.0e38f, mx1 = -3.0e38f;
        #pragma unroll
        for (int nt = 0; nt < 16; nt++) {
            int nc = kc * 128 + nt * 8 + (lane & 3) * 2;
            int f0 = misk[nc], f1 = misk[nc + 1];
            s[nt][0] = f0 ? -1e10f : s[nt][0] * 0.125f;
            s[nt][1] = f1 ? -1e10f : s[nt][1] * 0.125f;
            s[nt][2] = f0 ? -1e10f : s[nt][2] * 0.125f;
            s[nt][3] = f1 ? -1e10f : s[nt][3] * 0.125f;
            mx0 = fmaxf(mx0, fmaxf(s[nt][0], s[nt][1]));
            mx1 = fmaxf(mx1, fmaxf(s[nt][2], s[nt][3]));
        }
        #pragma unroll
        for (int of = 1; of <= 2; of <<= 1) {
            mx0 = fmaxf(mx0, __shfl_xor_sync(0xffffffffu, mx0, of));
            mx1 = fmaxf(mx1, __shfl_xor_sync(0xffffffffu, mx1, of));
        }
        float mn0 = fmaxf(mrow0, mx0), mn1 = fmaxf(mrow1, mx1);
        float al0 = exp2f((mrow0 - mn0) * LOG2E);
        float al1 = exp2f((mrow1 - mn1) * LOG2E);
        mrow0 = mn0; mrow1 = mn1;

        float sum0 = 0.f, sum1 = 0.f;
        #pragma unroll
        for (int nt = 0; nt < 16; nt++) {
            s[nt][0] = exp2f((s[nt][0] - mn0) * LOG2E);
            s[nt][1] = exp2f((s[nt][1] - mn0) * LOG2E);
            s[nt][2] = exp2f((s[nt][2] - mn1) * LOG2E);
            s[nt][3] = exp2f((s[nt][3] - mn1) * LOG2E);
            sum0 += s[nt][0] + s[nt][1];
            sum1 += s[nt][2] + s[nt][3];
        }
        #pragma unroll
        for (int of = 1; of <= 2; of <<= 1) {
            sum0 += __shfl_xor_sync(0xffffffffu, sum0, of);
            sum1 += __shfl_xor_sync(0xffffffffu, sum1, of);
        }
        lrow0 = lrow0 * al0 + sum0;
        lrow1 = lrow1 * al1 + sum1;

        #pragma unroll
        for (int t = 0; t < 8; t++) {
            o[t][0] *= al0; o[t][1] *= al0; o[t][2] *= al1; o[t][3] *= al1;
        }

        #pragma unroll
        for (int kg = 0; kg < 8; kg++) {
            uint32_t a[4];
            a[0] = packh2(s[kg * 2][0],     s[kg * 2][1]);
            a[1] = packh2(s[kg * 2][2],     s[kg * 2][3]);
            a[2] = packh2(s[kg * 2 + 1][0], s[kg * 2 + 1][1]);
            a[3] = packh2(s[kg * 2 + 1][2], s[kg * 2 + 1][3]);
            #pragma unroll
            for (int vn = 0; vn < 4; vn++) {
                uint32_t bf[4];
                int row = kg * 16 + (lane & 7) + ((lane >> 3) & 1) * 8;
                int c = vn * 2 + (lane >> 4);
                ldsm4t(bf, vB + row * 128 + ((c ^ (row & 7)) * 16));
                hmma(o[vn * 2 + 0], a, bf[0], bf[1]);
                hmma(o[vn * 2 + 1], a, bf[2], bf[3]);
            }
        }
        __syncthreads();
    }

    float inv0 = 1.f / lrow0, inv1 = 1.f / lrow1;
    int m = m0 + w * 16 + (lane >> 2);
    #pragma unroll
    for (int t = 0; t < 8; t++) {
        int hd = t * 8 + (lane & 3) * 2;
        *(__half2*)&g_xh[((size_t)(b * SSQ + m)) * DDQ + h * HDQ + hd] =
            __floats2half2_rn(o[t][0] * inv0, o[t][1] * inv0);
        *(__half2*)&g_xh[((size_t)(b * SSQ + m + 8)) * DDQ + h * HDQ + hd] =
            __floats2half2_rn(o[t][2] * inv1, o[t][3] * inv1);
    }
}

// ================= elementwise / reduction kernels ===========================
__inline__ __device__ float blockReduceSum128(float val) {
    __shared__ float sh[4];
    int lane = threadIdx.x & 31, w = threadIdx.x >> 5;
    #pragma unroll
    for (int o = 16; o; o >>= 1) val += __shfl_xor_sync(0xffffffffu, val, o);
    if (lane == 0) sh[w] = val;
    __syncthreads();
    float r = sh[0] + sh[1] + sh[2] + sh[3];
    __syncthreads();
    return r;
}

// fused: res = x + PE; tgt(fp16) = LN(res)*g + b.  one block (128 thr) per row.
__global__ void k_addpos_ln(const float* __restrict__ x, __half* __restrict__ tgt,
                            const float* __restrict__ gm, const float* __restrict__ bt) {
    int row = blockIdx.x;
    int s = row % SSQ;
    int t = threadIdx.x;
    int c = t * 4;
    float4 v = ((const float4*)(x + (size_t)row * DDQ))[t];
    float pe[4];
    #pragma unroll
    for (int i = 0; i < 4; i++) {
        int ci = c + i;
        float inv = exp2f(-((float)(2 * ci) * (1.0f / 512.0f)) * 13.2877123795494f);
        float ang = (float)s * inv;
        pe[i] = (ci & 1) ? cosf(ang) : sinf(ang);
    }
    v.x += pe[0]; v.y += pe[1]; v.z += pe[2]; v.w += pe[3];
    ((float4*)(g_res + (size_t)row * DDQ))[t] = v;

    float sm = v.x + v.y + v.z + v.w;
    float mean = blockReduceSum128(sm) * (1.0f / DDQ);
    float dx = v.x - mean, dy = v.y - mean, dz = v.z - mean, dw = v.w - mean;
    float s2 = dx*dx + dy*dy + dz*dz + dw*dw;
    float var = blockReduceSum128(s2) * (1.0f / DDQ);
    float inv = rsqrtf(var + 1e-5f);
    float ox = dx * inv * gm[c+0] + bt[c+0];
    float oy = dy * inv * gm[c+1] + bt[c+1];
    float oz = dz * inv * gm[c+2] + bt[c+2];
    float ow = dw * inv * gm[c+3] + bt[c+3];
    __half2* hp = (__half2*)(tgt + (size_t)row * DDQ + c);
    hp[0] = __floats2half2_rn(ox, oy);
    hp[1] = __floats2half2_rn(oz, ow);
}

// fused: res += Y(fp16); tgt(fp16) = LN(res)*g + b.  one block (128 thr) per row.
__global__ void k_addln(const __half* __restrict__ y, __half* __restrict__ tgt,
                        const float* __restrict__ gm, const float* __restrict__ bt) {
    int row = blockIdx.x;
    int t = threadIdx.x;
    int c = t * 4;
    float4 v = ((const float4*)(g_res + (size_t)row * DDQ))[t];
    uint2 raw = *(const uint2*)&y[(size_t)row * DDQ + c];
    __half2 y01 = *reinterpret_cast<__half2*>(&raw.x);
    __half2 y23 = *reinterpret_cast<__half2*>(&raw.y);
    float2 f01 = __half22float2(y01), f23 = __half22float2(y23);
    v.x += f01.x; v.y += f01.y; v.z += f23.x; v.w += f23.y;
    ((float4*)(g_res + (size_t)row * DDQ))[t] = v;

    float sm = v.x + v.y + v.z + v.w;
    float mean = blockReduceSum128(sm) * (1.0f / DDQ);
    float dx = v.x - mean, dy = v.y - mean, dz = v.z - mean, dw = v.w - mean;
    float s2 = dx*dx + dy*dy + dz*dz + dw*dw;
    float var = blockReduceSum128(s2) * (1.0f / DDQ);
    float inv = rsqrtf(var + 1e-5f);
    float ox = dx * inv * gm[c+0] + bt[c+0];
    float oy = dy * inv * gm[c+1] + bt[c+1];
    float oz = dz * inv * gm[c+2] + bt[c+2];
    float ow = dw * inv * gm[c+3] + bt[c+3];
    __half2* hp = (__half2*)(tgt + (size_t)row * DDQ + c);
    hp[0] = __floats2half2_rn(ox, oy);
    hp[1] = __floats2half2_rn(oz, ow);
}

// depthwise conv (K=7, same padding), fp16 in/out.
// thread = 4 channels x 4 consecutive s positions (10 row-loads / 16 outputs).
__global__ void __launch_bounds__(256)
k_dwconv_h(const __half* __restrict__ in, const float* __restrict__ dw) {
    int idx = blockIdx.x * 256 + threadIdx.x;
    if (idx >= (MMQ / 4) * 128) return;
    int c4 = (idx & 127) * 4;
    int bs4 = idx >> 7;
    const int SC = SSQ / 4;
    int b = bs4 / SC, s0 = (bs4 - b * SC) * 4;

    float w[4][KKQ];
    #pragma unroll
    for (int i = 0; i < 4; i++)
        #pragma unroll
        for (int k = 0; k < KKQ; k++)
            w[i][k] = dw[(c4 + i) * KKQ + k];

    float acc[4][4] = {};
    #pragma unroll
    for (int r = 0; r < 10; r++) {
        int ss = s0 - 3 + r;
        if (ss >= 0 && ss < SSQ) {
            uint2 raw = *(const uint2*)&in[(((size_t)b * SSQ + ss) << 9) + c4];
            __half2 h01 = *reinterpret_cast<__half2*>(&raw.x);
            __half2 h23 = *reinterpret_cast<__half2*>(&raw.y);
            float2 f01 = __half22float2(h01), f23 = __half22float2(h23);
            #pragma unroll
            for (int j = 0; j < 4; j++) {
                int t = r - j;
                if (t >= 0 && t < KKQ) {
                    acc[j][0] += f01.x * w[0][t];
                    acc[j][1] += f01.y * w[1][t];
                    acc[j][2] += f23.x * w[2][t];
                    acc[j][3] += f23.y * w[3][t];
                }
            }
        }
    }
    #pragma unroll
    for (int j = 0; j < 4; j++) {
        __half2 o01 = __floats2half2_rn(acc[j][0], acc[j][1]);
        __half2 o23 = __floats2half2_rn(acc[j][2], acc[j][3]);
        uint2 o;
        o.x = *reinterpret_cast<uint32_t*>(&o01);
        o.y = *reinterpret_cast<uint32_t*>(&o23);
        *(uint2*)&g_xh[(((size_t)b * SSQ + s0 + j) << 9) + c4] = o;
    }
}

// single fused fp32->fp16 weight conversion for all 9 matrices (float4)
__global__ void k_f2h_all(const float* __restrict__ pw_w, const float* __restrict__ wq,
                          const float* __restrict__ wk, const float* __restrict__ wv,
                          const float* __restrict__ wo, const float* __restrict__ fw) {
    const int WSZ4 = (DDQ * DDQ) / 4;
    int idx4 = blockIdx.x * 256 + threadIdx.x;
    if (idx4 >= 9 * WSZ4) return;
    int seg = idx4 / WSZ4;
    int off4 = idx4 - seg * WSZ4;
    const float* src;
    if (seg < 4)      src = pw_w + (size_t)seg * DDQ * DDQ;
    else if (seg == 4) src = wq;
    else if (seg == 5) src = wk;
    else if (seg == 6) src = wv;
    else if (seg == 7) src = wo;
    else               src = fw;
    float4 v = ((const float4*)src)[off4];
    __half2 h01 = __floats2half2_rn(v.x, v.y), h23 = __floats2half2_rn(v.z, v.w);
    uint2 o;
    o.x = *reinterpret_cast<uint32_t*>(&h01);
    o.y = *reinterpret_cast<uint32_t*>(&h23);
    *(uint2*)&g_wh[((size_t)seg * DDQ * DDQ) + off4 * 4] = o;
}

// ---------------- host orchestration -----------------------------------------
extern "C" void kernel_launch(void* const* d_in, const int* in_sizes, int n_in,
                              void* d_out, int out_size) {
    const float* x    = (const float*)d_in[0];
    const int*   mask = (const int*)  d_in[1];
    const float* dw_w = (const float*)d_in[2];
    const float* pw_w = (const float*)d_in[3];
    const float* pw_b = (const float*)d_in[4];
    const float* cg   = (const float*)d_in[5];
    const float* cb   = (const float*)d_in[6];
    const float* pg   = (const float*)d_in[7];
    const float* pb   = (const float*)d_in[8];
    const float* wq   = (const float*)d_in[9];
    const float* bq   = (const float*)d_in[10];
    const float* wk   = (const float*)d_in[11];
    const float* bk   = (const float*)d_in[12];
    const float* wv   = (const float*)d_in[13];
    const float* bv   = (const float*)d_in[14];
    const float* wo   = (const float*)d_in[15];
    const float* bo   = (const float*)d_in[16];
    const float* fg   = (const float*)d_in[17];
    const float* fb   = (const float*)d_in[18];
    const float* fw   = (const float*)d_in[19];
    const float* fbi  = (const float*)d_in[20];
    float* out = (float*)d_out;

    float* p_res;
    __half *p_xh, *p_yh, *p_wh, *p_qh, *p_qkv;
    cudaGetSymbolAddress((void**)&p_res, g_res);
    cudaGetSymbolAddress((void**)&p_xh,  g_xh);
    cudaGetSymbolAddress((void**)&p_yh,  g_yh);
    cudaGetSymbolAddress((void**)&p_wh,  g_wh);
    cudaGetSymbolAddress((void**)&p_qh,  g_qh);
    cudaGetSymbolAddress((void**)&p_qkv, g_qkv);

    const int WSZ = DDQ * DDQ;  // 262144
    dim3 dg(4, 96);             // N=512: N/128, M/64
    dim3 dgq(12, 48);           // QKV: N=1536/128, M/128 -> 576 blocks, 1.95 waves

    // 0. weights -> fp16
    k_f2h_all<<<(9 * WSZ / 4 + 255) / 256, 256>>>(pw_w, wq, wk, wv, wo, fw);

    // 1. res = x + PE ; LN -> fp16 (conv input in g_qh)
    k_addpos_ln<<<MMQ, 128>>>(x, p_qh, pg, pb);

    // 2. conv stack: dwconv -> GEMM(Y fp16) -> addln (res += Y; LN)
    for (int l = 0; l < LLQ; l++) {
        k_dwconv_h<<<(MMQ / 4) * 128 / 256, 256>>>(p_qh, dw_w + l * DDQ * KKQ);
        k_gemm_h<1, 0><<<dg, 256>>>(p_xh, p_wh + (size_t)l * WSZ,
                                    pw_b + l * DDQ, nullptr, nullptr, p_yh);
        k_addln<<<MMQ, 128>>>(p_yh, (l < LLQ - 1) ? p_qh : p_xh,
                              cg + l * DDQ, cb + l * DDQ);
    }

    // 3. attention: fused QKV (wave-packed tile) -> flash -> wo GEMM -> addln
    k_gemm_qkv<<<dgq, 256>>>(p_xh, p_wh + 4 * (size_t)WSZ, bq, bk, bv, p_qkv);
    k_flash<<<dim3(3, BHQ), 256>>>(mask);
    k_gemm_h<0, 0><<<dg, 256>>>(p_xh, p_wh + 7 * (size_t)WSZ,
                                bo, nullptr, nullptr, p_yh);
    k_addln<<<MMQ, 128>>>(p_yh, p_xh, fg, fb);

    // 4. feedforward final: out = relu(LN @ fw^T + fb) + res  (fp32 epilogue)
    k_gemm_h<1, 2><<<dg, 256>>>(p_xh, p_wh + 8 * (size_t)WSZ,
                                fbi, p_res, out, nullptr);
}

// round 16
// speedup vs baseline: 1.1277x; 1.0476x over previous
#include <cuda_runtime.h>
#include <cuda_fp16.h>
#include <math.h>
#include <stdint.h>

// Problem constants
#define BB   16
#define SSQ  384
#define DDQ  512
#define HHQ  8
#define HDQ  64
#define LLQ  4
#define KKQ  7
#define MMQ  (BB*SSQ)      // 6144 rows
#define BHQ  (BB*HHQ)      // 128 batch*heads

// ---------------- scratch (device globals; no allocation allowed) -----------
__device__ float g_res[MMQ*DDQ];                        // fp32 residual spine
__device__ __half g_xh[MMQ*DDQ];                        // fp16 GEMM A operand
__device__ __half g_yh[MMQ*DDQ];                        // fp16 GEMM Y output
__device__ __half g_wh[9*DDQ*DDQ];                      // fp16 weights
__device__ __half g_qh[MMQ*DDQ];                        // LN16 out (conv input)
__device__ __half g_qkv[3*MMQ*DDQ];                     // fused QKV, head-major

// ================= low-level helpers =========================================
__device__ __forceinline__ uint32_t smem_u32(const void* p) {
    uint32_t a;
    asm("{ .reg .u64 t; cvta.to.shared.u64 t, %1; cvt.u32.u64 %0, t; }" : "=r"(a) : "l"(p));
    return a;
}
__device__ __forceinline__ void cpa16(uint32_t dst, const void* src) {
    asm volatile("cp.async.cg.shared.global [%0], [%1], 16;" :: "r"(dst), "l"(src) : "memory");
}
#define CP_COMMIT() asm volatile("cp.async.commit_group;" ::: "memory")
#define CP_WAIT(n)  asm volatile("cp.async.wait_group %0;" :: "n"(n) : "memory")

__device__ __forceinline__ void ldsm4(uint32_t* r, uint32_t addr) {
    asm volatile("ldmatrix.sync.aligned.m8n8.x4.shared.b16 {%0,%1,%2,%3}, [%4];"
                 : "=r"(r[0]), "=r"(r[1]), "=r"(r[2]), "=r"(r[3]) : "r"(addr));
}
__device__ __forceinline__ void ldsm4t(uint32_t* r, uint32_t addr) {
    asm volatile("ldmatrix.sync.aligned.m8n8.x4.trans.shared.b16 {%0,%1,%2,%3}, [%4];"
                 : "=r"(r[0]), "=r"(r[1]), "=r"(r[2]), "=r"(r[3]) : "r"(addr));
}
__device__ __forceinline__ void hmma(float* d, const uint32_t* a, uint32_t b0, uint32_t b1) {
    asm volatile(
        "mma.sync.aligned.m16n8k16.row.col.f32.f16.f16.f32 "
        "{%0,%1,%2,%3}, {%4,%5,%6,%7}, {%8,%9}, {%0,%1,%2,%3};"
        : "+f"(d[0]), "+f"(d[1]), "+f"(d[2]), "+f"(d[3])
        : "r"(a[0]), "r"(a[1]), "r"(a[2]), "r"(a[3]), "r"(b0), "r"(b1));
}
__device__ __forceinline__ uint32_t packh2(float x, float y) {
    __half2 h = __floats2half2_rn(x, y);
    return *reinterpret_cast<uint32_t*>(&h);
}

// ================= dense GEMM (N=512 layers): BM=64 BN=128 BK=64 =============
// 256 threads (8 warps, 2m x 4n, warp tile 32x32), cp.async 3-stage, 3 blk/SM.
// MODE 0: Y fp16 (bias+optional relu)   MODE 2: fp32 +res (final FF layer)
template<int RELU, int MODE>
__global__ void __launch_bounds__(256, 3)
k_gemm_h(const __half* __restrict__ X, const __half* __restrict__ W,
         const float* __restrict__ bias, const float* __restrict__ res,
         float* __restrict__ outf, __half* __restrict__ outh) {
    __shared__ __half As[3][64 * 64];
    __shared__ __half Bs[3][128 * 64];
    const int tid = threadIdx.x, lane = tid & 31, wid = tid >> 5;
    const int wm = wid >> 2, wn = wid & 3;
    const int m0 = blockIdx.y * 64, n0 = blockIdx.x * 128;
    float acc[2][4][4] = {};

    const uint32_t aB[3] = { smem_u32(&As[0][0]), smem_u32(&As[1][0]), smem_u32(&As[2][0]) };
    const uint32_t bB[3] = { smem_u32(&Bs[0][0]), smem_u32(&Bs[1][0]), smem_u32(&Bs[2][0]) };

    auto load_stage = [&](int kt, int st) {
        #pragma unroll
        for (int i = 0; i < 2; i++) {
            int q = tid + i * 256; int r = q >> 3, c = q & 7;
            cpa16(aB[st] + r * 128 + ((c ^ (r & 7)) * 16),
                  X + (size_t)(m0 + r) * DDQ + kt * 64 + c * 8);
        }
        #pragma unroll
        for (int i = 0; i < 4; i++) {
            int q = tid + i * 256; int r = q >> 3, c = q & 7;
            cpa16(bB[st] + r * 128 + ((c ^ (r & 7)) * 16),
                  W + (size_t)(n0 + r) * DDQ + kt * 64 + c * 8);
        }
        CP_COMMIT();
    };

    load_stage(0, 0);
    load_stage(1, 1);

    #pragma unroll 1
    for (int kt = 0; kt < 8; kt++) {
        int st = kt % 3;
        if (kt < 7) { CP_WAIT(1); } else { CP_WAIT(0); }
        __syncthreads();
        if (kt + 2 < 8) load_stage(kt + 2, (kt + 2) % 3);

        #pragma unroll
        for (int ks = 0; ks < 4; ks++) {
            uint32_t a[2][4], bfr[2][4];
            #pragma unroll
            for (int mt = 0; mt < 2; mt++) {
                int r = wm * 32 + mt * 16 + (lane & 15);
                int c = ks * 2 + (lane >> 4);
                ldsm4(a[mt], aB[st] + r * 128 + ((c ^ (r & 7)) * 16));
            }
            #pragma unroll
            for (int np = 0; np < 2; np++) {
                int nr = wn * 32 + np * 16 + (lane & 7) + ((lane >> 4) << 3);
                int c = ks * 2 + ((lane >> 3) & 1);
                ldsm4(bfr[np], bB[st] + nr * 128 + ((c ^ (nr & 7)) * 16));
            }
            #pragma unroll
            for (int mt = 0; mt < 2; mt++)
                #pragma unroll
                for (int nt = 0; nt < 4; nt++)
                    hmma(acc[mt][nt], a[mt],
                         bfr[nt >> 1][(nt & 1) * 2], bfr[nt >> 1][(nt & 1) * 2 + 1]);
        }
    }

    // epilogue
    #pragma unroll
    for (int mt = 0; mt < 2; mt++) {
        int r = m0 + wm * 32 + mt * 16 + (lane >> 2);
        #pragma unroll
        for (int nt = 0; nt < 4; nt++) {
            int cl = wn * 32 + nt * 8 + (lane & 3) * 2;
            int n = n0 + cl;
            float b0 = bias[n], b1 = bias[n + 1];
            float v00 = acc[mt][nt][0] + b0, v01 = acc[mt][nt][1] + b1;
            float v10 = acc[mt][nt][2] + b0, v11 = acc[mt][nt][3] + b1;
            if (RELU) {
                v00 = fmaxf(v00, 0.f); v01 = fmaxf(v01, 0.f);
                v10 = fmaxf(v10, 0.f); v11 = fmaxf(v11, 0.f);
            }
            if (MODE == 0) {
                *(__half2*)&outh[(size_t)r * DDQ + n] = __floats2half2_rn(v00, v01);
                *(__half2*)&outh[(size_t)(r + 8) * DDQ + n] = __floats2half2_rn(v10, v11);
            } else {
                float2 r0 = *(const float2*)&res[(size_t)r * DDQ + n];
                float2 r1 = *(const float2*)&res[(size_t)(r + 8) * DDQ + n];
                *(float2*)&outf[(size_t)r * DDQ + n] = make_float2(v00 + r0.x, v01 + r0.y);
                *(float2*)&outf[(size_t)(r + 8) * DDQ + n] = make_float2(v10 + r1.x, v11 + r1.y);
            }
        }
    }
}

// ================= QKV GEMM (N=1536): BM=128 BN=128 BK=64 ====================
// 256 threads (8 warps, 4m x 2n, warp tile 32x64), cp.async 3-stage, 2 blk/SM.
// grid (12,48) = 576 blocks = 1.95 waves of 296 slots (near-perfect packing).
__global__ void __launch_bounds__(256, 2)
k_gemm_qkv(const __half* __restrict__ X, const __half* __restrict__ W,
           const float* __restrict__ bias, const float* __restrict__ bias2,
           const float* __restrict__ bias3, __half* __restrict__ outh) {
    __shared__ __half As[3][128 * 64];
    __shared__ __half Bs[3][128 * 64];
    const int tid = threadIdx.x, lane = tid & 31, wid = tid >> 5;
    const int wm = wid >> 1, wn = wid & 1;
    const int m0 = blockIdx.y * 128, n0 = blockIdx.x * 128;
    float acc[2][8][4] = {};

    const uint32_t aB[3] = { smem_u32(&As[0][0]), smem_u32(&As[1][0]), smem_u32(&As[2][0]) };
    const uint32_t bB[3] = { smem_u32(&Bs[0][0]), smem_u32(&Bs[1][0]), smem_u32(&Bs[2][0]) };

    auto load_stage = [&](int kt, int st) {
        #pragma unroll
        for (int i = 0; i < 4; i++) {
            int q = tid + i * 256; int r = q >> 3, c = q & 7;
            cpa16(aB[st] + r * 128 + ((c ^ (r & 7)) * 16),
                  X + (size_t)(m0 + r) * DDQ + kt * 64 + c * 8);
        }
        #pragma unroll
        for (int i = 0; i < 4; i++) {
            int q = tid + i * 256; int r = q >> 3, c = q & 7;
            cpa16(bB[st] + r * 128 + ((c ^ (r & 7)) * 16),
                  W + (size_t)(n0 + r) * DDQ + kt * 64 + c * 8);
        }
        CP_COMMIT();
    };

    load_stage(0, 0);
    load_stage(1, 1);

    #pragma unroll 1
    for (int kt = 0; kt < 8; kt++) {
        int st = kt % 3;
        if (kt < 7) { CP_WAIT(1); } else { CP_WAIT(0); }
        __syncthreads();
        if (kt + 2 < 8) load_stage(kt + 2, (kt + 2) % 3);

        #pragma unroll
        for (int ks = 0; ks < 4; ks++) {
            uint32_t a[2][4], bfr[4][4];
            #pragma unroll
            for (int mt = 0; mt < 2; mt++) {
                int r = wm * 32 + mt * 16 + (lane & 15);
                int c = ks * 2 + (lane >> 4);
                ldsm4(a[mt], aB[st] + r * 128 + ((c ^ (r & 7)) * 16));
            }
            #pragma unroll
            for (int np = 0; np < 4; np++) {
                int nr = wn * 64 + np * 16 + (lane & 7) + ((lane >> 4) << 3);
                int c = ks * 2 + ((lane >> 3) & 1);
                ldsm4(bfr[np], bB[st] + nr * 128 + ((c ^ (nr & 7)) * 16));
            }
            #pragma unroll
            for (int mt = 0; mt < 2; mt++)
                #pragma unroll
                for (int nt = 0; nt < 8; nt++)
                    hmma(acc[mt][nt], a[mt],
                         bfr[nt >> 1][(nt & 1) * 2], bfr[nt >> 1][(nt & 1) * 2 + 1]);
        }
    }

    // epilogue: head-major scatter with per-matrix bias
    const int mat = n0 >> 9;
    const int col0 = n0 & 511;
    const float* bp = (mat == 0) ? bias : ((mat == 1) ? bias2 : bias3);
    __half* ob = outh + (size_t)mat * MMQ * DDQ;
    #pragma unroll
    for (int mt = 0; mt < 2; mt++) {
        int r = m0 + wm * 32 + mt * 16 + (lane >> 2);
        #pragma unroll
        for (int nt = 0; nt < 8; nt++) {
            int cl = wn * 64 + nt * 8 + (lane & 3) * 2;
            int col = col0 + cl;
            float b0 = bp[col], b1 = bp[col + 1];
            float v00 = acc[mt][nt][0] + b0, v01 = acc[mt][nt][1] + b1;
            float v10 = acc[mt][nt][2] + b0, v11 = acc[mt][nt][3] + b1;
            int h = col >> 6, hd = col & 63;
            int b_ = r / SSQ, s = r % SSQ;
            *(__half2*)&ob[(((size_t)(b_ * HHQ + h) * SSQ + s) << 6) + hd] =
                __floats2half2_rn(v00, v01);
            int b2 = (r + 8) / SSQ, s2 = (r + 8) % SSQ;
            *(__half2*)&ob[(((size_t)(b2 * HHQ + h) * SSQ + s2) << 6) + hd] =
                __floats2half2_rn(v10, v11);
        }
    }
}

// ================= flash attention ==========================================
__global__ void __launch_bounds__(256)
k_flash(const int* __restrict__ mask) {
    __shared__ __half Qs[128 * 64];
    __shared__ __half Ks[128 * 64];
    __shared__ __half Vs[128 * 64];
    __shared__ int misk[SSQ];
    const int bh = blockIdx.y, b = bh >> 3, h = bh & 7;
    const __half* Q = g_qkv + (size_t)bh * SSQ * HDQ;
    const __half* K = g_qkv + (size_t)MMQ * DDQ + (size_t)bh * SSQ * HDQ;
    const __half* V = g_qkv + 2 * (size_t)MMQ * DDQ + (size_t)bh * SSQ * HDQ;
    const int m0 = blockIdx.x * 128;
    const int tid = threadIdx.x, lane = tid & 31, w = tid >> 5;
    const uint32_t qB = smem_u32(Qs), kB = smem_u32(Ks), vB = smem_u32(Vs);

    for (int i = tid; i < SSQ; i += 256) misk[i] = mask[b * SSQ + i];

    #pragma unroll
    for (int i = 0; i < 4; i++) {
        int q = tid + i * 256; int r = q >> 3, c = q & 7;
        cpa16(qB + r * 128 + ((c ^ (r & 7)) * 16), Q + (size_t)(m0 + r) * HDQ + c * 8);
    }

    float o[8][4] = {};
    float mrow0 = -3.0e38f, mrow1 = -3.0e38f, lrow0 = 0.f, lrow1 = 0.f;
    const float LOG2E = 1.4426950408889634f;

    #pragma unroll 1
    for (int kc = 0; kc < 3; kc++) {
        #pragma unroll
        for (int i = 0; i < 4; i++) {
            int q = tid + i * 256; int r = q >> 3, c = q & 7;
            cpa16(kB + r * 128 + ((c ^ (r & 7)) * 16),
                  K + (size_t)(kc * 128 + r) * HDQ + c * 8);
            cpa16(vB + r * 128 + ((c ^ (r & 7)) * 16),
                  V + (size_t)(kc * 128 + r) * HDQ + c * 8);
        }
        CP_COMMIT(); CP_WAIT(0);
        __syncthreads();

        float s[16][4] = {};
        #pragma unroll
        for (int ks = 0; ks < 4; ks++) {
            uint32_t a[4];
            { int r = w * 16 + (lane & 15);
              int c = ks * 2 + (lane >> 4);
              ldsm4(a, qB + r * 128 + ((c ^ (r & 7)) * 16)); }
            #pragma unroll
            for (int np = 0; np < 8; np++) {
                uint32_t bf[4];
                int nr = np * 16 + (lane & 7) + ((lane >> 4) << 3);
                int c = ks * 2 + ((lane >> 3) & 1);
                ldsm4(bf, kB + nr * 128 + ((c ^ (nr & 7)) * 16));
                hmma(s[np * 2 + 0], a, bf[0], bf[1]);
                hmma(s[np * 2 + 1], a, bf[2], bf[3]);
            }
        }

        float mx0 = -3.0e38f, mx1 = -3.0e38f;
        #pragma unroll
        for (int nt = 0; nt < 16; nt++) {
            int nc = kc * 128 + nt * 8 + (lane & 3) * 2;
            int f0 = misk[nc], f1 = misk[nc + 1];
            s[nt][0] = f0 ? -1e10f : s[nt][0] * 0.125f;
            s[nt][1] = f1 ? -1e10f : s[nt][1] * 0.125f;
            s[nt][2] = f0 ? -1e10f : s[nt][2] * 0.125f;
            s[nt][3] = f1 ? -1e10f : s[nt][3] * 0.125f;
            mx0 = fmaxf(mx0, fmaxf(s[nt][0], s[nt][1]));
            mx1 = fmaxf(mx1, fmaxf(s[nt][2], s[nt][3]));
        }
        #pragma unroll
        for (int of = 1; of <= 2; of <<= 1) {
            mx0 = fmaxf(mx0, __shfl_xor_sync(0xffffffffu, mx0, of));
            mx1 = fmaxf(mx1, __shfl_xor_sync(0xffffffffu, mx1, of));
        }
        float mn0 = fmaxf(mrow0, mx0), mn1 = fmaxf(mrow1, mx1);
        float al0 = exp2f((mrow0 - mn0) * LOG2E);
        float al1 = exp2f((mrow1 - mn1) * LOG2E);
        mrow0 = mn0; mrow1 = mn1;

        float sum0 = 0.f, sum1 = 0.f;
        #pragma unroll
        for (int nt = 0; nt < 16; nt++) {
            s[nt][0] = exp2f((s[nt][0] - mn0) * LOG2E);
            s[nt][1] = exp2f((s[nt][1] - mn0) * LOG2E);
            s[nt][2] = exp2f((s[nt][2] - mn1) * LOG2E);
            s[nt][3] = exp2f((s[nt][3] - mn1) * LOG2E);
            sum0 += s[nt][0] + s[nt][1];
            sum1 += s[nt][2] + s[nt][3];
        }
        #pragma unroll
        for (int of = 1; of <= 2; of <<= 1) {
            sum0 += __shfl_xor_sync(0xffffffffu, sum0, of);
            sum1 += __shfl_xor_sync(0xffffffffu, sum1, of);
        }
        lrow0 = lrow0 * al0 + sum0;
        lrow1 = lrow1 * al1 + sum1;

        #pragma unroll
        for (int t = 0; t < 8; t++) {
            o[t][0] *= al0; o[t][1] *= al0; o[t][2] *= al1; o[t][3] *= al1;
        }

        #pragma unroll
        for (int kg = 0; kg < 8; kg++) {
            uint32_t a[4];
            a[0] = packh2(s[kg * 2][0],     s[kg * 2][1]);
            a[1] = packh2(s[kg * 2][2],     s[kg * 2][3]);
            a[2] = packh2(s[kg * 2 + 1][0], s[kg * 2 + 1][1]);
            a[3] = packh2(s[kg * 2 + 1][2], s[kg * 2 + 1][3]);
            #pragma unroll
            for (int vn = 0; vn < 4; vn++) {
                uint32_t bf[4];
                int row = kg * 16 + (lane & 7) + ((lane >> 3) & 1) * 8;
                int c = vn * 2 + (lane >> 4);
                ldsm4t(bf, vB + row * 128 + ((c ^ (row & 7)) * 16));
                hmma(o[vn * 2 + 0], a, bf[0], bf[1]);
                hmma(o[vn * 2 + 1], a, bf[2], bf[3]);
            }
        }
        __syncthreads();
    }

    float inv0 = 1.f / lrow0, inv1 = 1.f / lrow1;
    int m = m0 + w * 16 + (lane >> 2);
    #pragma unroll
    for (int t = 0; t < 8; t++) {
        int hd = t * 8 + (lane & 3) * 2;
        *(__half2*)&g_xh[((size_t)(b * SSQ + m)) * DDQ + h * HDQ + hd] =
            __floats2half2_rn(o[t][0] * inv0, o[t][1] * inv0);
        *(__half2*)&g_xh[((size_t)(b * SSQ + m + 8)) * DDQ + h * HDQ + hd] =
            __floats2half2_rn(o[t][2] * inv1, o[t][3] * inv1);
    }
}

// ================= elementwise / reduction kernels ===========================
__inline__ __device__ float blockReduceSum128(float val) {
    __shared__ float sh[4];
    int lane = threadIdx.x & 31, w = threadIdx.x >> 5;
    #pragma unroll
    for (int o = 16; o; o >>= 1) val += __shfl_xor_sync(0xffffffffu, val, o);
    if (lane == 0) sh[w] = val;
    __syncthreads();
    float r = sh[0] + sh[1] + sh[2] + sh[3];
    __syncthreads();
    return r;
}

// fused: res = x + PE; tgt(fp16) = LN(res)*g + b.  one block (128 thr) per row.
__global__ void k_addpos_ln(const float* __restrict__ x, __half* __restrict__ tgt,
                            const float* __restrict__ gm, const float* __restrict__ bt) {
    int row = blockIdx.x;
    int s = row % SSQ;
    int t = threadIdx.x;
    int c = t * 4;
    float4 v = ((const float4*)(x + (size_t)row * DDQ))[t];
    float pe[4];
    #pragma unroll
    for (int i = 0; i < 4; i++) {
        int ci = c + i;
        float inv = exp2f(-((float)(2 * ci) * (1.0f / 512.0f)) * 13.2877123795494f);
        float ang = (float)s * inv;
        pe[i] = (ci & 1) ? cosf(ang) : sinf(ang);
    }
    v.x += pe[0]; v.y += pe[1]; v.z += pe[2]; v.w += pe[3];
    ((float4*)(g_res + (size_t)row * DDQ))[t] = v;

    float sm = v.x + v.y + v.z + v.w;
    float mean = blockReduceSum128(sm) * (1.0f / DDQ);
    float dx = v.x - mean, dy = v.y - mean, dz = v.z - mean, dw = v.w - mean;
    float s2 = dx*dx + dy*dy + dz*dz + dw*dw;
    float var = blockReduceSum128(s2) * (1.0f / DDQ);
    float inv = rsqrtf(var + 1e-5f);
    float ox = dx * inv * gm[c+0] + bt[c+0];
    float oy = dy * inv * gm[c+1] + bt[c+1];
    float oz = dz * inv * gm[c+2] + bt[c+2];
    float ow = dw * inv * gm[c+3] + bt[c+3];
    __half2* hp = (__half2*)(tgt + (size_t)row * DDQ + c);
    hp[0] = __floats2half2_rn(ox, oy);
    hp[1] = __floats2half2_rn(oz, ow);
}

// fused: res += Y(fp16); tgt(fp16) = LN(res)*g + b.  one block (128 thr) per row.
__global__ void k_addln(const __half* __restrict__ y, __half* __restrict__ tgt,
                        const float* __restrict__ gm, const float* __restrict__ bt) {
    int row = blockIdx.x;
    int t = threadIdx.x;
    int c = t * 4;
    float4 v = ((const float4*)(g_res + (size_t)row * DDQ))[t];
    uint2 raw = *(const uint2*)&y[(size_t)row * DDQ + c];
    __half2 y01 = *reinterpret_cast<__half2*>(&raw.x);
    __half2 y23 = *reinterpret_cast<__half2*>(&raw.y);
    float2 f01 = __half22float2(y01), f23 = __half22float2(y23);
    v.x += f01.x; v.y += f01.y; v.z += f23.x; v.w += f23.y;
    ((float4*)(g_res + (size_t)row * DDQ))[t] = v;

    float sm = v.x + v.y + v.z + v.w;
    float mean = blockReduceSum128(sm) * (1.0f / DDQ);
    float dx = v.x - mean, dy = v.y - mean, dz = v.z - mean, dw = v.w - mean;
    float s2 = dx*dx + dy*dy + dz*dz + dw*dw;
    float var = blockReduceSum128(s2) * (1.0f / DDQ);
    float inv = rsqrtf(var + 1e-5f);
    float ox = dx * inv * gm[c+0] + bt[c+0];
    float oy = dy * inv * gm[c+1] + bt[c+1];
    float oz = dz * inv * gm[c+2] + bt[c+2];
    float ow = dw * inv * gm[c+3] + bt[c+3];
    __half2* hp = (__half2*)(tgt + (size_t)row * DDQ + c);
    hp[0] = __floats2half2_rn(ox, oy);
    hp[1] = __floats2half2_rn(oz, ow);
}

// depthwise conv (K=7, same padding), fp16 in/out, smem-staged.
// block = (128-ch group, 64-s tile, batch). slab 70x128 staged once; each
// thread computes 4 channels x 8 s positions from smem.
__global__ void __launch_bounds__(256)
k_dwconv_s(const __half* __restrict__ in, const float* __restrict__ dw) {
    __shared__ __half tile[70 * 128];
    const int c0 = blockIdx.x * 128;
    const int s0 = blockIdx.y * 64;
    const int b  = blockIdx.z;
    const int tid = threadIdx.x;

    // stage 70 rows x 128 ch (each row = 16 chunks of 16B), zero-padded halo
    #pragma unroll
    for (int i = 0; i < 5; i++) {
        int q = tid + i * 256;                // 0..1279, need 1120
        if (q < 70 * 16) {
            int r = q >> 4, ck = q & 15;
            int s = s0 - 3 + r;
            uint4 v = make_uint4(0u, 0u, 0u, 0u);
            if (s >= 0 && s < SSQ)
                v = *(const uint4*)&in[(((size_t)b * SSQ + s) << 9) + c0 + ck * 8];
            *(uint4*)&tile[r * 128 + ck * 8] = v;
        }
    }
    __syncthreads();

    const int lc = (tid & 31) * 4;            // local channel 0..124
    const int sg = tid >> 5;                  // s-group 0..7 (8 s each)

    float w[4][KKQ];
    #pragma unroll
    for (int i = 0; i < 4; i++)
        #pragma unroll
        for (int k = 0; k < KKQ; k++)
            w[i][k] = dw[(c0 + lc + i) * KKQ + k];

    #pragma unroll
    for (int j = 0; j < 8; j++) {
        float a0 = 0.f, a1 = 0.f, a2 = 0.f, a3 = 0.f;
        #pragma unroll
        for (int k = 0; k < KKQ; k++) {
            uint2 raw = *(const uint2*)&tile[(sg * 8 + j + k) * 128 + lc];
            float2 f01 = __half22float2(*reinterpret_cast<__half2*>(&raw.x));
            float2 f23 = __half22float2(*reinterpret_cast<__half2*>(&raw.y));
            a0 += f01.x * w[0][k]; a1 += f01.y * w[1][k];
            a2 += f23.x * w[2][k]; a3 += f23.y * w[3][k];
        }
        __half2 o01 = __floats2half2_rn(a0, a1), o23 = __floats2half2_rn(a2, a3);
        uint2 o;
        o.x = *reinterpret_cast<uint32_t*>(&o01);
        o.y = *reinterpret_cast<uint32_t*>(&o23);
        int s = s0 + sg * 8 + j;
        *(uint2*)&g_xh[(((size_t)b * SSQ + s) << 9) + c0 + lc] = o;
    }
}

// single fused fp32->fp16 weight conversion for all 9 matrices (float4)
__global__ void k_f2h_all(const float* __restrict__ pw_w, const float* __restrict__ wq,
                          const float* __restrict__ wk, const float* __restrict__ wv,
                          const float* __restrict__ wo, const float* __restrict__ fw) {
    const int WSZ4 = (DDQ * DDQ) / 4;
    int idx4 = blockIdx.x * 256 + threadIdx.x;
    if (idx4 >= 9 * WSZ4) return;
    int seg = idx4 / WSZ4;
    int off4 = idx4 - seg * WSZ4;
    const float* src;
    if (seg < 4)      src = pw_w + (size_t)seg * DDQ * DDQ;
    else if (seg == 4) src = wq;
    else if (seg == 5) src = wk;
    else if (seg == 6) src = wv;
    else if (seg == 7) src = wo;
    else               src = fw;
    float4 v = ((const float4*)src)[off4];
    __half2 h01 = __floats2half2_rn(v.x, v.y), h23 = __floats2half2_rn(v.z, v.w);
    uint2 o;
    o.x = *reinterpret_cast<uint32_t*>(&h01);
    o.y = *reinterpret_cast<uint32_t*>(&h23);
    *(uint2*)&g_wh[((size_t)seg * DDQ * DDQ) + off4 * 4] = o;
}

// ---------------- host orchestration -----------------------------------------
extern "C" void kernel_launch(void* const* d_in, const int* in_sizes, int n_in,
                              void* d_out, int out_size) {
    const float* x    = (const float*)d_in[0];
    const int*   mask = (const int*)  d_in[1];
    const float* dw_w = (const float*)d_in[2];
    const float* pw_w = (const float*)d_in[3];
    const float* pw_b = (const float*)d_in[4];
    const float* cg   = (const float*)d_in[5];
    const float* cb   = (const float*)d_in[6];
    const float* pg   = (const float*)d_in[7];
    const float* pb   = (const float*)d_in[8];
    const float* wq   = (const float*)d_in[9];
    const float* bq   = (const float*)d_in[10];
    const float* wk   = (const float*)d_in[11];
    const float* bk   = (const float*)d_in[12];
    const float* wv   = (const float*)d_in[13];
    const float* bv   = (const float*)d_in[14];
    const float* wo   = (const float*)d_in[15];
    const float* bo   = (const float*)d_in[16];
    const float* fg   = (const float*)d_in[17];
    const float* fb   = (const float*)d_in[18];
    const float* fw   = (const float*)d_in[19];
    const float* fbi  = (const float*)d_in[20];
    float* out = (float*)d_out;

    float* p_res;
    __half *p_xh, *p_yh, *p_wh, *p_qh, *p_qkv;
    cudaGetSymbolAddress((void**)&p_res, g_res);
    cudaGetSymbolAddress((void**)&p_xh,  g_xh);
    cudaGetSymbolAddress((void**)&p_yh,  g_yh);
    cudaGetSymbolAddress((void**)&p_wh,  g_wh);
    cudaGetSymbolAddress((void**)&p_qh,  g_qh);
    cudaGetSymbolAddress((void**)&p_qkv, g_qkv);

    const int WSZ = DDQ * DDQ;  // 262144
    dim3 dg(4, 96);             // N=512: N/128, M/64
    dim3 dgq(12, 48);           // QKV: 576 blocks, 1.95 waves
    dim3 dgc(4, 6, BB);         // dwconv: ch-group, s-tile, batch

    // 0. weights -> fp16
    k_f2h_all<<<(9 * WSZ / 4 + 255) / 256, 256>>>(pw_w, wq, wk, wv, wo, fw);

    // 1. res = x + PE ; LN -> fp16 (conv input in g_qh)
    k_addpos_ln<<<MMQ, 128>>>(x, p_qh, pg, pb);

    // 2. conv stack: smem-staged dwconv -> GEMM(Y fp16) -> addln (res += Y; LN)
    for (int l = 0; l < LLQ; l++) {
        k_dwconv_s<<<dgc, 256>>>(p_qh, dw_w + l * DDQ * KKQ);
        k_gemm_h<1, 0><<<dg, 256>>>(p_xh, p_wh + (size_t)l * WSZ,
                                    pw_b + l * DDQ, nullptr, nullptr, p_yh);
        k_addln<<<MMQ, 128>>>(p_yh, (l < LLQ - 1) ? p_qh : p_xh,
                              cg + l * DDQ, cb + l * DDQ);
    }

    // 3. attention: fused QKV (wave-packed tile) -> flash -> wo GEMM -> addln
    k_gemm_qkv<<<dgq, 256>>>(p_xh, p_wh + 4 * (size_t)WSZ, bq, bk, bv, p_qkv);
    k_flash<<<dim3(3, BHQ), 256>>>(mask);
    k_gemm_h<0, 0><<<dg, 256>>>(p_xh, p_wh + 7 * (size_t)WSZ,
                                bo, nullptr, nullptr, p_yh);
    k_addln<<<MMQ, 128>>>(p_yh, p_xh, fg, fb);

    // 4. feedforward final: out = relu(LN @ fw^T + fb) + res  (fp32 epilogue)
    k_gemm_h<1, 2><<<dg, 256>>>(p_xh, p_wh + 8 * (size_t)WSZ,
                                fbi, p_res, out, nullptr);
}

// round 17
// speedup vs baseline: 1.1456x; 1.0159x over previous
#include <cuda_runtime.h>
#include <cuda_fp16.h>
#include <math.h>
#include <stdint.h>

// Problem constants
#define BB   16
#define SSQ  384
#define DDQ  512
#define HHQ  8
#define HDQ  64
#define LLQ  4
#define KKQ  7
#define MMQ  (BB*SSQ)      // 6144 rows
#define BHQ  (BB*HHQ)      // 128 batch*heads

// ---------------- scratch (device globals; no allocation allowed) -----------
__device__ __half g_res[MMQ*DDQ];                       // fp16 residual spine
__device__ __half g_xh[MMQ*DDQ];                        // fp16 GEMM A operand
__device__ __half g_yh[MMQ*DDQ];                        // fp16 GEMM Y output
__device__ __half g_wh[9*DDQ*DDQ];                      // fp16 weights
__device__ __half g_qh[MMQ*DDQ];                        // LN16 out (conv input)
__device__ __half g_qkv[3*MMQ*DDQ];                     // fused QKV, head-major

// ================= low-level helpers =========================================
__device__ __forceinline__ uint32_t smem_u32(const void* p) {
    uint32_t a;
    asm("{ .reg .u64 t; cvta.to.shared.u64 t, %1; cvt.u32.u64 %0, t; }" : "=r"(a) : "l"(p));
    return a;
}
__device__ __forceinline__ void cpa16(uint32_t dst, const void* src) {
    asm volatile("cp.async.cg.shared.global [%0], [%1], 16;" :: "r"(dst), "l"(src) : "memory");
}
#define CP_COMMIT() asm volatile("cp.async.commit_group;" ::: "memory")
#define CP_WAIT(n)  asm volatile("cp.async.wait_group %0;" :: "n"(n) : "memory")

__device__ __forceinline__ void ldsm4(uint32_t* r, uint32_t addr) {
    asm volatile("ldmatrix.sync.aligned.m8n8.x4.shared.b16 {%0,%1,%2,%3}, [%4];"
                 : "=r"(r[0]), "=r"(r[1]), "=r"(r[2]), "=r"(r[3]) : "r"(addr));
}
__device__ __forceinline__ void ldsm4t(uint32_t* r, uint32_t addr) {
    asm volatile("ldmatrix.sync.aligned.m8n8.x4.trans.shared.b16 {%0,%1,%2,%3}, [%4];"
                 : "=r"(r[0]), "=r"(r[1]), "=r"(r[2]), "=r"(r[3]) : "r"(addr));
}
__device__ __forceinline__ void hmma(float* d, const uint32_t* a, uint32_t b0, uint32_t b1) {
    asm volatile(
        "mma.sync.aligned.m16n8k16.row.col.f32.f16.f16.f32 "
        "{%0,%1,%2,%3}, {%4,%5,%6,%7}, {%8,%9}, {%0,%1,%2,%3};"
        : "+f"(d[0]), "+f"(d[1]), "+f"(d[2]), "+f"(d[3])
        : "r"(a[0]), "r"(a[1]), "r"(a[2]), "r"(a[3]), "r"(b0), "r"(b1));
}
__device__ __forceinline__ uint32_t packh2(float x, float y) {
    __half2 h = __floats2half2_rn(x, y);
    return *reinterpret_cast<uint32_t*>(&h);
}

// ================= dense GEMM (N=512 layers): BM=64 BN=128 BK=64 =============
// 256 threads (8 warps, 2m x 4n, warp tile 32x32), cp.async 3-stage, 3 blk/SM.
// MODE 0: Y fp16 (bias+optional relu)   MODE 2: fp32 out +res(fp16) (final FF)
template<int RELU, int MODE>
__global__ void __launch_bounds__(256, 3)
k_gemm_h(const __half* __restrict__ X, const __half* __restrict__ W,
         const float* __restrict__ bias, const __half* __restrict__ res,
         float* __restrict__ outf, __half* __restrict__ outh) {
    __shared__ __half As[3][64 * 64];
    __shared__ __half Bs[3][128 * 64];
    const int tid = threadIdx.x, lane = tid & 31, wid = tid >> 5;
    const int wm = wid >> 2, wn = wid & 3;
    const int m0 = blockIdx.y * 64, n0 = blockIdx.x * 128;
    float acc[2][4][4] = {};

    const uint32_t aB[3] = { smem_u32(&As[0][0]), smem_u32(&As[1][0]), smem_u32(&As[2][0]) };
    const uint32_t bB[3] = { smem_u32(&Bs[0][0]), smem_u32(&Bs[1][0]), smem_u32(&Bs[2][0]) };

    auto load_stage = [&](int kt, int st) {
        #pragma unroll
        for (int i = 0; i < 2; i++) {
            int q = tid + i * 256; int r = q >> 3, c = q & 7;
            cpa16(aB[st] + r * 128 + ((c ^ (r & 7)) * 16),
                  X + (size_t)(m0 + r) * DDQ + kt * 64 + c * 8);
        }
        #pragma unroll
        for (int i = 0; i < 4; i++) {
            int q = tid + i * 256; int r = q >> 3, c = q & 7;
            cpa16(bB[st] + r * 128 + ((c ^ (r & 7)) * 16),
                  W + (size_t)(n0 + r) * DDQ + kt * 64 + c * 8);
        }
        CP_COMMIT();
    };

    load_stage(0, 0);
    load_stage(1, 1);

    #pragma unroll 1
    for (int kt = 0; kt < 8; kt++) {
        int st = kt % 3;
        if (kt < 7) { CP_WAIT(1); } else { CP_WAIT(0); }
        __syncthreads();
        if (kt + 2 < 8) load_stage(kt + 2, (kt + 2) % 3);

        #pragma unroll
        for (int ks = 0; ks < 4; ks++) {
            uint32_t a[2][4], bfr[2][4];
            #pragma unroll
            for (int mt = 0; mt < 2; mt++) {
                int r = wm * 32 + mt * 16 + (lane & 15);
                int c = ks * 2 + (lane >> 4);
                ldsm4(a[mt], aB[st] + r * 128 + ((c ^ (r & 7)) * 16));
            }
            #pragma unroll
            for (int np = 0; np < 2; np++) {
                int nr = wn * 32 + np * 16 + (lane & 7) + ((lane >> 4) << 3);
                int c = ks * 2 + ((lane >> 3) & 1);
                ldsm4(bfr[np], bB[st] + nr * 128 + ((c ^ (nr & 7)) * 16));
            }
            #pragma unroll
            for (int mt = 0; mt < 2; mt++)
                #pragma unroll
                for (int nt = 0; nt < 4; nt++)
                    hmma(acc[mt][nt], a[mt],
                         bfr[nt >> 1][(nt & 1) * 2], bfr[nt >> 1][(nt & 1) * 2 + 1]);
        }
    }

    // epilogue
    #pragma unroll
    for (int mt = 0; mt < 2; mt++) {
        int r = m0 + wm * 32 + mt * 16 + (lane >> 2);
        #pragma unroll
        for (int nt = 0; nt < 4; nt++) {
            int cl = wn * 32 + nt * 8 + (lane & 3) * 2;
            int n = n0 + cl;
            float b0 = bias[n], b1 = bias[n + 1];
            float v00 = acc[mt][nt][0] + b0, v01 = acc[mt][nt][1] + b1;
            float v10 = acc[mt][nt][2] + b0, v11 = acc[mt][nt][3] + b1;
            if (RELU) {
                v00 = fmaxf(v00, 0.f); v01 = fmaxf(v01, 0.f);
                v10 = fmaxf(v10, 0.f); v11 = fmaxf(v11, 0.f);
            }
            if (MODE == 0) {
                *(__half2*)&outh[(size_t)r * DDQ + n] = __floats2half2_rn(v00, v01);
                *(__half2*)&outh[(size_t)(r + 8) * DDQ + n] = __floats2half2_rn(v10, v11);
            } else {
                __half2 r0 = *(const __half2*)&res[(size_t)r * DDQ + n];
                __half2 r1 = *(const __half2*)&res[(size_t)(r + 8) * DDQ + n];
                float2 f0 = __half22float2(r0), f1 = __half22float2(r1);
                *(float2*)&outf[(size_t)r * DDQ + n] = make_float2(v00 + f0.x, v01 + f0.y);
                *(float2*)&outf[(size_t)(r + 8) * DDQ + n] = make_float2(v10 + f1.x, v11 + f1.y);
            }
        }
    }
}

// ================= QKV GEMM (N=1536): BM=128 BN=128 BK=64 ====================
__global__ void __launch_bounds__(256, 2)
k_gemm_qkv(const __half* __restrict__ X, const __half* __restrict__ W,
           const float* __restrict__ bias, const float* __restrict__ bias2,
           const float* __restrict__ bias3, __half* __restrict__ outh) {
    __shared__ __half As[3][128 * 64];
    __shared__ __half Bs[3][128 * 64];
    const int tid = threadIdx.x, lane = tid & 31, wid = tid >> 5;
    const int wm = wid >> 1, wn = wid & 1;
    const int m0 = blockIdx.y * 128, n0 = blockIdx.x * 128;
    float acc[2][8][4] = {};

    const uint32_t aB[3] = { smem_u32(&As[0][0]), smem_u32(&As[1][0]), smem_u32(&As[2][0]) };
    const uint32_t bB[3] = { smem_u32(&Bs[0][0]), smem_u32(&Bs[1][0]), smem_u32(&Bs[2][0]) };

    auto load_stage = [&](int kt, int st) {
        #pragma unroll
        for (int i = 0; i < 4; i++) {
            int q = tid + i * 256; int r = q >> 3, c = q & 7;
            cpa16(aB[st] + r * 128 + ((c ^ (r & 7)) * 16),
                  X + (size_t)(m0 + r) * DDQ + kt * 64 + c * 8);
        }
        #pragma unroll
        for (int i = 0; i < 4; i++) {
            int q = tid + i * 256; int r = q >> 3, c = q & 7;
            cpa16(bB[st] + r * 128 + ((c ^ (r & 7)) * 16),
                  W + (size_t)(n0 + r) * DDQ + kt * 64 + c * 8);
        }
        CP_COMMIT();
    };

    load_stage(0, 0);
    load_stage(1, 1);

    #pragma unroll 1
    for (int kt = 0; kt < 8; kt++) {
        int st = kt % 3;
        if (kt < 7) { CP_WAIT(1); } else { CP_WAIT(0); }
        __syncthreads();
        if (kt + 2 < 8) load_stage(kt + 2, (kt + 2) % 3);

        #pragma unroll
        for (int ks = 0; ks < 4; ks++) {
            uint32_t a[2][4], bfr[4][4];
            #pragma unroll
            for (int mt = 0; mt < 2; mt++) {
                int r = wm * 32 + mt * 16 + (lane & 15);
                int c = ks * 2 + (lane >> 4);
                ldsm4(a[mt], aB[st] + r * 128 + ((c ^ (r & 7)) * 16));
            }
            #pragma unroll
            for (int np = 0; np < 4; np++) {
                int nr = wn * 64 + np * 16 + (lane & 7) + ((lane >> 4) << 3);
                int c = ks * 2 + ((lane >> 3) & 1);
                ldsm4(bfr[np], bB[st] + nr * 128 + ((c ^ (nr & 7)) * 16));
            }
            #pragma unroll
            for (int mt = 0; mt < 2; mt++)
                #pragma unroll
                for (int nt = 0; nt < 8; nt++)
                    hmma(acc[mt][nt], a[mt],
                         bfr[nt >> 1][(nt & 1) * 2], bfr[nt >> 1][(nt & 1) * 2 + 1]);
        }
    }

    // epilogue: head-major scatter with per-matrix bias
    const int mat = n0 >> 9;
    const int col0 = n0 & 511;
    const float* bp = (mat == 0) ? bias : ((mat == 1) ? bias2 : bias3);
    __half* ob = outh + (size_t)mat * MMQ * DDQ;
    #pragma unroll
    for (int mt = 0; mt < 2; mt++) {
        int r = m0 + wm * 32 + mt * 16 + (lane >> 2);
        #pragma unroll
        for (int nt = 0; nt < 8; nt++) {
            int cl = wn * 64 + nt * 8 + (lane & 3) * 2;
            int col = col0 + cl;
            float b0 = bp[col], b1 = bp[col + 1];
            float v00 = acc[mt][nt][0] + b0, v01 = acc[mt][nt][1] + b1;
            float v10 = acc[mt][nt][2] + b0, v11 = acc[mt][nt][3] + b1;
            int h = col >> 6, hd = col & 63;
            int b_ = r / SSQ, s = r % SSQ;
            *(__half2*)&ob[(((size_t)(b_ * HHQ + h) * SSQ + s) << 6) + hd] =
                __floats2half2_rn(v00, v01);
            int b2 = (r + 8) / SSQ, s2 = (r + 8) % SSQ;
            *(__half2*)&ob[(((size_t)(b2 * HHQ + h) * SSQ + s2) << 6) + hd] =
                __floats2half2_rn(v10, v11);
        }
    }
}

// ================= flash attention ==========================================
__global__ void __launch_bounds__(256)
k_flash(const int* __restrict__ mask) {
    __shared__ __half Qs[128 * 64];
    __shared__ __half Ks[128 * 64];
    __shared__ __half Vs[128 * 64];
    __shared__ int misk[SSQ];
    const int bh = blockIdx.y, b = bh >> 3, h = bh & 7;
    const __half* Q = g_qkv + (size_t)bh * SSQ * HDQ;
    const __half* K = g_qkv + (size_t)MMQ * DDQ + (size_t)bh * SSQ * HDQ;
    const __half* V = g_qkv + 2 * (size_t)MMQ * DDQ + (size_t)bh * SSQ * HDQ;
    const int m0 = blockIdx.x * 128;
    const int tid = threadIdx.x, lane = tid & 31, w = tid >> 5;
    const uint32_t qB = smem_u32(Qs), kB = smem_u32(Ks), vB = smem_u32(Vs);

    for (int i = tid; i < SSQ; i += 256) misk[i] = mask[b * SSQ + i];

    #pragma unroll
    for (int i = 0; i < 4; i++) {
        int q = tid + i * 256; int r = q >> 3, c = q & 7;
        cpa16(qB + r * 128 + ((c ^ (r & 7)) * 16), Q + (size_t)(m0 + r) * HDQ + c * 8);
    }

    float o[8][4] = {};
    float mrow0 = -3.0e38f, mrow1 = -3.0e38f, lrow0 = 0.f, lrow1 = 0.f;
    const float LOG2E = 1.4426950408889634f;

    #pragma unroll 1
    for (int kc = 0; kc < 3; kc++) {
        #pragma unroll
        for (int i = 0; i < 4; i++) {
            int q = tid + i * 256; int r = q >> 3, c = q & 7;
            cpa16(kB + r * 128 + ((c ^ (r & 7)) * 16),
                  K + (size_t)(kc * 128 + r) * HDQ + c * 8);
            cpa16(vB + r * 128 + ((c ^ (r & 7)) * 16),
                  V + (size_t)(kc * 128 + r) * HDQ + c * 8);
        }
        CP_COMMIT(); CP_WAIT(0);
        __syncthreads();

        float s[16][4] = {};
        #pragma unroll
        for (int ks = 0; ks < 4; ks++) {
            uint32_t a[4];
            { int r = w * 16 + (lane & 15);
              int c = ks * 2 + (lane >> 4);
              ldsm4(a, qB + r * 128 + ((c ^ (r & 7)) * 16)); }
            #pragma unroll
            for (int np = 0; np < 8; np++) {
                uint32_t bf[4];
                int nr = np * 16 + (lane & 7) + ((lane >> 4) << 3);
                int c = ks * 2 + ((lane >> 3) & 1);
                ldsm4(bf, kB + nr * 128 + ((c ^ (nr & 7)) * 16));
                hmma(s[np * 2 + 0], a, bf[0], bf[1]);
                hmma(s[np * 2 + 1], a, bf[2], bf[3]);
            }
        }

        float mx0 = -3.0e38f, mx1 = -3.0e38f;
        #pragma unroll
        for (int nt = 0; nt < 16; nt++) {
            int nc = kc * 128 + nt * 8 + (lane & 3) * 2;
            int f0 = misk[nc], f1 = misk[nc + 1];
            s[nt][0] = f0 ? -1e10f : s[nt][0] * 0.125f;
            s[nt][1] = f1 ? -1e10f : s[nt][1] * 0.125f;
            s[nt][2] = f0 ? -1e10f : s[nt][2] * 0.125f;
            s[nt][3] = f1 ? -1e10f : s[nt][3] * 0.125f;
            mx0 = fmaxf(mx0, fmaxf(s[nt][0], s[nt][1]));
            mx1 = fmaxf(mx1, fmaxf(s[nt][2], s[nt][3]));
        }
        #pragma unroll
        for (int of = 1; of <= 2; of <<= 1) {
            mx0 = fmaxf(mx0, __shfl_xor_sync(0xffffffffu, mx0, of));
            mx1 = fmaxf(mx1, __shfl_xor_sync(0xffffffffu, mx1, of));
        }
        float mn0 = fmaxf(mrow0, mx0), mn1 = fmaxf(mrow1, mx1);
        float al0 = exp2f((mrow0 - mn0) * LOG2E);
        float al1 = exp2f((mrow1 - mn1) * LOG2E);
        mrow0 = mn0; mrow1 = mn1;

        float sum0 = 0.f, sum1 = 0.f;
        #pragma unroll
        for (int nt = 0; nt < 16; nt++) {
            s[nt][0] = exp2f((s[nt][0] - mn0) * LOG2E);
            s[nt][1] = exp2f((s[nt][1] - mn0) * LOG2E);
            s[nt][2] = exp2f((s[nt][2] - mn1) * LOG2E);
            s[nt][3] = exp2f((s[nt][3] - mn1) * LOG2E);
            sum0 += s[nt][0] + s[nt][1];
            sum1 += s[nt][2] + s[nt][3];
        }
        #pragma unroll
        for (int of = 1; of <= 2; of <<= 1) {
            sum0 += __shfl_xor_sync(0xffffffffu, sum0, of);
            sum1 += __shfl_xor_sync(0xffffffffu, sum1, of);
        }
        lrow0 = lrow0 * al0 + sum0;
        lrow1 = lrow1 * al1 + sum1;

        #pragma unroll
        for (int t = 0; t < 8; t++) {
            o[t][0] *= al0; o[t][1] *= al0; o[t][2] *= al1; o[t][3] *= al1;
        }

        #pragma unroll
        for (int kg = 0; kg < 8; kg++) {
            uint32_t a[4];
            a[0] = packh2(s[kg * 2][0],     s[kg * 2][1]);
            a[1] = packh2(s[kg * 2][2],     s[kg * 2][3]);
            a[2] = packh2(s[kg * 2 + 1][0], s[kg * 2 + 1][1]);
            a[3] = packh2(s[kg * 2 + 1][2], s[kg * 2 + 1][3]);
            #pragma unroll
            for (int vn = 0; vn < 4; vn++) {
                uint32_t bf[4];
                int row = kg * 16 + (lane & 7) + ((lane >> 3) & 1) * 8;
                int c = vn * 2 + (lane >> 4);
                ldsm4t(bf, vB + row * 128 + ((c ^ (row & 7)) * 16));
                hmma(o[vn * 2 + 0], a, bf[0], bf[1]);
                hmma(o[vn * 2 + 1], a, bf[2], bf[3]);
            }
        }
        __syncthreads();
    }

    float inv0 = 1.f / lrow0, inv1 = 1.f / lrow1;
    int m = m0 + w * 16 + (lane >> 2);
    #pragma unroll
    for (int t = 0; t < 8; t++) {
        int hd = t * 8 + (lane & 3) * 2;
        *(__half2*)&g_xh[((size_t)(b * SSQ + m)) * DDQ + h * HDQ + hd] =
            __floats2half2_rn(o[t][0] * inv0, o[t][1] * inv0);
        *(__half2*)&g_xh[((size_t)(b * SSQ + m + 8)) * DDQ + h * HDQ + hd] =
            __floats2half2_rn(o[t][2] * inv1, o[t][3] * inv1);
    }
}

// ================= elementwise / reduction kernels ===========================
__inline__ __device__ float blockReduceSum128(float val) {
    __shared__ float sh[4];
    int lane = threadIdx.x & 31, w = threadIdx.x >> 5;
    #pragma unroll
    for (int o = 16; o; o >>= 1) val += __shfl_xor_sync(0xffffffffu, val, o);
    if (lane == 0) sh[w] = val;
    __syncthreads();
    float r = sh[0] + sh[1] + sh[2] + sh[3];
    __syncthreads();
    return r;
}

// fused: res(fp16) = x + PE; tgt(fp16) = LN(res)*g + b.  one block per row.
__global__ void k_addpos_ln(const float* __restrict__ x, __half* __restrict__ tgt,
                            const float* __restrict__ gm, const float* __restrict__ bt) {
    int row = blockIdx.x;
    int s = row % SSQ;
    int t = threadIdx.x;
    int c = t * 4;
    float4 v = ((const float4*)(x + (size_t)row * DDQ))[t];
    float pe[4];
    #pragma unroll
    for (int i = 0; i < 4; i++) {
        int ci = c + i;
        float inv = exp2f(-((float)(2 * ci) * (1.0f / 512.0f)) * 13.2877123795494f);
        float ang = (float)s * inv;
        pe[i] = (ci & 1) ? cosf(ang) : sinf(ang);
    }
    v.x += pe[0]; v.y += pe[1]; v.z += pe[2]; v.w += pe[3];
    {
        __half2* rp = (__half2*)(g_res + (size_t)row * DDQ + c);
        rp[0] = __floats2half2_rn(v.x, v.y);
        rp[1] = __floats2half2_rn(v.z, v.w);
    }

    float sm = v.x + v.y + v.z + v.w;
    float mean = blockReduceSum128(sm) * (1.0f / DDQ);
    float dx = v.x - mean, dy = v.y - mean, dz = v.z - mean, dw = v.w - mean;
    float s2 = dx*dx + dy*dy + dz*dz + dw*dw;
    float var = blockReduceSum128(s2) * (1.0f / DDQ);
    float inv = rsqrtf(var + 1e-5f);
    float ox = dx * inv * gm[c+0] + bt[c+0];
    float oy = dy * inv * gm[c+1] + bt[c+1];
    float oz = dz * inv * gm[c+2] + bt[c+2];
    float ow = dw * inv * gm[c+3] + bt[c+3];
    __half2* hp = (__half2*)(tgt + (size_t)row * DDQ + c);
    hp[0] = __floats2half2_rn(ox, oy);
    hp[1] = __floats2half2_rn(oz, ow);
}

// fused: res(fp16) += Y(fp16); tgt(fp16) = LN(res)*g + b.  one block per row.
__global__ void k_addln(const __half* __restrict__ y, __half* __restrict__ tgt,
                        const float* __restrict__ gm, const float* __restrict__ bt) {
    int row = blockIdx.x;
    int t = threadIdx.x;
    int c = t * 4;
    uint2 rr = *(const uint2*)&g_res[(size_t)row * DDQ + c];
    uint2 ry = *(const uint2*)&y[(size_t)row * DDQ + c];
    float2 r01 = __half22float2(*reinterpret_cast<__half2*>(&rr.x));
    float2 r23 = __half22float2(*reinterpret_cast<__half2*>(&rr.y));
    float2 y01 = __half22float2(*reinterpret_cast<__half2*>(&ry.x));
    float2 y23 = __half22float2(*reinterpret_cast<__half2*>(&ry.y));
    float vx = r01.x + y01.x, vy = r01.y + y01.y;
    float vz = r23.x + y23.x, vw = r23.y + y23.y;
    {
        __half2* rp = (__half2*)(g_res + (size_t)row * DDQ + c);
        rp[0] = __floats2half2_rn(vx, vy);
        rp[1] = __floats2half2_rn(vz, vw);
    }

    float sm = vx + vy + vz + vw;
    float mean = blockReduceSum128(sm) * (1.0f / DDQ);
    float dx = vx - mean, dy = vy - mean, dz = vz - mean, dw = vw - mean;
    float s2 = dx*dx + dy*dy + dz*dz + dw*dw;
    float var = blockReduceSum128(s2) * (1.0f / DDQ);
    float inv = rsqrtf(var + 1e-5f);
    float ox = dx * inv * gm[c+0] + bt[c+0];
    float oy = dy * inv * gm[c+1] + bt[c+1];
    float oz = dz * inv * gm[c+2] + bt[c+2];
    float ow = dw * inv * gm[c+3] + bt[c+3];
    __half2* hp = (__half2*)(tgt + (size_t)row * DDQ + c);
    hp[0] = __floats2half2_rn(ox, oy);
    hp[1] = __floats2half2_rn(oz, ow);
}

// depthwise conv (K=7, same padding), fp16 in/out, smem-staged.
__global__ void __launch_bounds__(256)
k_dwconv_s(const __half* __restrict__ in, const float* __restrict__ dw) {
    __shared__ __half tile[70 * 128];
    const int c0 = blockIdx.x * 128;
    const int s0 = blockIdx.y * 64;
    const int b  = blockIdx.z;
    const int tid = threadIdx.x;

    #pragma unroll
    for (int i = 0; i < 5; i++) {
        int q = tid + i * 256;
        if (q < 70 * 16) {
            int r = q >> 4, ck = q & 15;
            int s = s0 - 3 + r;
            uint4 v = make_uint4(0u, 0u, 0u, 0u);
            if (s >= 0 && s < SSQ)
                v = *(const uint4*)&in[(((size_t)b * SSQ + s) << 9) + c0 + ck * 8];
            *(uint4*)&tile[r * 128 + ck * 8] = v;
        }
    }
    __syncthreads();

    const int lc = (tid & 31) * 4;
    const int sg = tid >> 5;

    float w[4][KKQ];
    #pragma unroll
    for (int i = 0; i < 4; i++)
        #pragma unroll
        for (int k = 0; k < KKQ; k++)
            w[i][k] = dw[(c0 + lc + i) * KKQ + k];

    #pragma unroll
    for (int j = 0; j < 8; j++) {
        float a0 = 0.f, a1 = 0.f, a2 = 0.f, a3 = 0.f;
        #pragma unroll
        for (int k = 0; k < KKQ; k++) {
            uint2 raw = *(const uint2*)&tile[(sg * 8 + j + k) * 128 + lc];
            float2 f01 = __half22float2(*reinterpret_cast<__half2*>(&raw.x));
            float2 f23 = __half22float2(*reinterpret_cast<__half2*>(&raw.y));
            a0 += f01.x * w[0][k]; a1 += f01.y * w[1][k];
            a2 += f23.x * w[2][k]; a3 += f23.y * w[3][k];
        }
        __half2 o01 = __floats2half2_rn(a0, a1), o23 = __floats2half2_rn(a2, a3);
        uint2 o;
        o.x = *reinterpret_cast<uint32_t*>(&o01);
        o.y = *reinterpret_cast<uint32_t*>(&o23);
        int s = s0 + sg * 8 + j;
        *(uint2*)&g_xh[(((size_t)b * SSQ + s) << 9) + c0 + lc] = o;
    }
}

// single fused fp32->fp16 weight conversion for all 9 matrices (float4)
__global__ void k_f2h_all(const float* __restrict__ pw_w, const float* __restrict__ wq,
                          const float* __restrict__ wk, const float* __restrict__ wv,
                          const float* __restrict__ wo, const float* __restrict__ fw) {
    const int WSZ4 = (DDQ * DDQ) / 4;
    int idx4 = blockIdx.x * 256 + threadIdx.x;
    if (idx4 >= 9 * WSZ4) return;
    int seg = idx4 / WSZ4;
    int off4 = idx4 - seg * WSZ4;
    const float* src;
    if (seg < 4)      src = pw_w + (size_t)seg * DDQ * DDQ;
    else if (seg == 4) src = wq;
    else if (seg == 5) src = wk;
    else if (seg == 6) src = wv;
    else if (seg == 7) src = wo;
    else               src = fw;
    float4 v = ((const float4*)src)[off4];
    __half2 h01 = __floats2half2_rn(v.x, v.y), h23 = __floats2half2_rn(v.z, v.w);
    uint2 o;
    o.x = *reinterpret_cast<uint32_t*>(&h01);
    o.y = *reinterpret_cast<uint32_t*>(&h23);
    *(uint2*)&g_wh[((size_t)seg * DDQ * DDQ) + off4 * 4] = o;
}

// ---------------- host orchestration -----------------------------------------
extern "C" void kernel_launch(void* const* d_in, const int* in_sizes, int n_in,
                              void* d_out, int out_size) {
    const float* x    = (const float*)d_in[0];
    const int*   mask = (const int*)  d_in[1];
    const float* dw_w = (const float*)d_in[2];
    const float* pw_w = (const float*)d_in[3];
    const float* pw_b = (const float*)d_in[4];
    const float* cg   = (const float*)d_in[5];
    const float* cb   = (const float*)d_in[6];
    const float* pg   = (const float*)d_in[7];
    const float* pb   = (const float*)d_in[8];
    const float* wq   = (const float*)d_in[9];
    const float* bq   = (const float*)d_in[10];
    const float* wk   = (const float*)d_in[11];
    const float* bk   = (const float*)d_in[12];
    const float* wv   = (const float*)d_in[13];
    const float* bv   = (const float*)d_in[14];
    const float* wo   = (const float*)d_in[15];
    const float* bo   = (const float*)d_in[16];
    const float* fg   = (const float*)d_in[17];
    const float* fb   = (const float*)d_in[18];
    const float* fw   = (const float*)d_in[19];
    const float* fbi  = (const float*)d_in[20];
    float* out = (float*)d_out;

    __half *p_res, *p_xh, *p_yh, *p_wh, *p_qh, *p_qkv;
    cudaGetSymbolAddress((void**)&p_res, g_res);
    cudaGetSymbolAddress((void**)&p_xh,  g_xh);
    cudaGetSymbolAddress((void**)&p_yh,  g_yh);
    cudaGetSymbolAddress((void**)&p_wh,  g_wh);
    cudaGetSymbolAddress((void**)&p_qh,  g_qh);
    cudaGetSymbolAddress((void**)&p_qkv, g_qkv);

    const int WSZ = DDQ * DDQ;  // 262144
    dim3 dg(4, 96);             // N=512: N/128, M/64
    dim3 dgq(12, 48);           // QKV: 576 blocks, 1.95 waves
    dim3 dgc(4, 6, BB);         // dwconv: ch-group, s-tile, batch

    // 0. weights -> fp16
    k_f2h_all<<<(9 * WSZ / 4 + 255) / 256, 256>>>(pw_w, wq, wk, wv, wo, fw);

    // 1. res = x + PE ; LN -> fp16 (conv input in g_qh)
    k_addpos_ln<<<MMQ, 128>>>(x, p_qh, pg, pb);

    // 2. conv stack: smem-staged dwconv -> GEMM(Y fp16) -> addln (res += Y; LN)
    for (int l = 0; l < LLQ; l++) {
        k_dwconv_s<<<dgc, 256>>>(p_qh, dw_w + l * DDQ * KKQ);
        k_gemm_h<1, 0><<<dg, 256>>>(p_xh, p_wh + (size_t)l * WSZ,
                                    pw_b + l * DDQ, nullptr, nullptr, p_yh);
        k_addln<<<MMQ, 128>>>(p_yh, (l < LLQ - 1) ? p_qh : p_xh,
                              cg + l * DDQ, cb + l * DDQ);
    }

    // 3. attention: fused QKV (wave-packed tile) -> flash -> wo GEMM -> addln
    k_gemm_qkv<<<dgq, 256>>>(p_xh, p_wh + 4 * (size_t)WSZ, bq, bk, bv, p_qkv);
    k_flash<<<dim3(3, BHQ), 256>>>(mask);
    k_gemm_h<0, 0><<<dg, 256>>>(p_xh, p_wh + 7 * (size_t)WSZ,
                                bo, nullptr, nullptr, p_yh);
    k_addln<<<MMQ, 128>>>(p_yh, p_xh, fg, fb);

    // 4. feedforward final: out = relu(LN @ fw^T + fb) + res  (fp32 epilogue)
    k_gemm_h<1, 2><<<dg, 256>>>(p_xh, p_wh + 8 * (size_t)WSZ,
                                fbi, p_res, out, nullptr);
}